// round 1
// baseline (speedup 1.0000x reference)
#include <cuda_runtime.h>
#include <cstdint>
#include <cstddef>

// ---------------- problem constants ----------------
#define NB    8
#define SEQ   1024
#define DM    512
#define NH    8
#define DKH   64
#define DI    2048
#define NE    24
#define CAP   171
#define TG    2048          // tokens per group (8 * 256)
#define NGRP  4
#define NROWS (NB*SEQ)      // 8192
#define EPSV  1e-6f

// ---------------- device scratch (no allocations allowed) ----------------
__device__ float g_q[NROWS*DM];
__device__ float g_k[NROWS*DM];
__device__ float g_v[NROWS*DM];
__device__ float g_ctx[NROWS*DM];
__device__ float g_tmp[NROWS*DM];
__device__ float g_res[NROWS*DM];     // post-attention LN (residual for MoE)
__device__ float g_y[NROWS*DM];       // MoE out + residual, pre final LN
__device__ float g_sloth[(size_t)NE*CAP*DI];
__device__ float g_sloty[(size_t)NE*CAP*DM];
__device__ float g_hpost[(size_t)TG*DI];
__device__ int   g_e1[TG], g_e2[TG], g_s1[TG], g_s2[TG];
__device__ float g_wa[TG], g_wb[TG];
__device__ int   g_rowg[NE*CAP];      // gather rows into g_res (global row)
__device__ int   g_rowl[NE*CAP];      // gather rows into g_hpost (local token)

// ---------------- helpers ----------------
__device__ __forceinline__ float blk_sum(float v, float* sb) {
    int lane = threadIdx.x & 31, wid = threadIdx.x >> 5;
    #pragma unroll
    for (int o = 16; o; o >>= 1) v += __shfl_down_sync(0xffffffffu, v, o);
    if (lane == 0) sb[wid] = v;
    __syncthreads();
    int nw = (blockDim.x + 31) >> 5;
    if (wid == 0) {
        float r = (lane < nw) ? sb[lane] : 0.f;
        #pragma unroll
        for (int o = 16; o; o >>= 1) r += __shfl_down_sync(0xffffffffu, r, o);
        if (lane == 0) sb[0] = r;
    }
    __syncthreads();
    float r = sb[0];
    __syncthreads();
    return r;
}

// ---------------- dense SGEMM: C[M,N] = A[M,K] @ B[K,N] (+epilogue) ----------------
// BM=128 BN=128 BK=8, 256 threads, 8x8 per thread. M%128==0, N%128==0, K%8==0.
// epi==1: C = relu(AB) + R
__global__ __launch_bounds__(256)
void sgemm128(const float* __restrict__ A, const float* __restrict__ B,
              float* __restrict__ C, int M, int N, int K,
              const float* __restrict__ R, int epi)
{
    __shared__ float As[8][128];
    __shared__ float Bs[8][128];
    const int tid = threadIdx.x;
    const int bx = blockIdx.x, by = blockIdx.y;
    const int trow = tid >> 4, tcol = tid & 15;

    float acc[8][8];
    #pragma unroll
    for (int i = 0; i < 8; i++)
        #pragma unroll
        for (int j = 0; j < 8; j++) acc[i][j] = 0.f;

    const int aRow = tid >> 1;
    const int aCol = (tid & 1) * 4;
    const int bRow = tid >> 5;
    const int bCol = (tid & 31) * 4;
    const float* Ap = A + (size_t)(by*128 + aRow)*K + aCol;
    const float* Bp = B + (size_t)bRow*N + bx*128 + bCol;

    for (int k0 = 0; k0 < K; k0 += 8) {
        float4 a4 = *(const float4*)(Ap + k0);
        float4 b4 = *(const float4*)(Bp + (size_t)k0*N);
        As[aCol+0][aRow] = a4.x; As[aCol+1][aRow] = a4.y;
        As[aCol+2][aRow] = a4.z; As[aCol+3][aRow] = a4.w;
        *(float4*)&Bs[bRow][bCol] = b4;
        __syncthreads();
        #pragma unroll
        for (int kk = 0; kk < 8; kk++) {
            float4 ar0 = *(const float4*)&As[kk][trow*8];
            float4 ar1 = *(const float4*)&As[kk][trow*8+4];
            float4 br0 = *(const float4*)&Bs[kk][tcol*8];
            float4 br1 = *(const float4*)&Bs[kk][tcol*8+4];
            float a_[8] = {ar0.x,ar0.y,ar0.z,ar0.w,ar1.x,ar1.y,ar1.z,ar1.w};
            float b_[8] = {br0.x,br0.y,br0.z,br0.w,br1.x,br1.y,br1.z,br1.w};
            #pragma unroll
            for (int i = 0; i < 8; i++)
                #pragma unroll
                for (int j = 0; j < 8; j++)
                    acc[i][j] = fmaf(a_[i], b_[j], acc[i][j]);
        }
        __syncthreads();
    }
    #pragma unroll
    for (int i = 0; i < 8; i++) {
        int row = by*128 + trow*8 + i;
        #pragma unroll
        for (int j = 0; j < 8; j += 4) {
            int col = bx*128 + tcol*8 + j;
            float4 v = make_float4(acc[i][j], acc[i][j+1], acc[i][j+2], acc[i][j+3]);
            if (epi == 1) {
                const float4 r = *(const float4*)&R[(size_t)row*N + col];
                v.x = fmaxf(v.x, 0.f) + r.x;
                v.y = fmaxf(v.y, 0.f) + r.y;
                v.z = fmaxf(v.z, 0.f) + r.z;
                v.w = fmaxf(v.w, 0.f) + r.w;
            }
            *(float4*)&C[(size_t)row*N + col] = v;
        }
    }
}

// ---------------- MoE gathered GEMM: C[e,r,:] = X[rowmap[e,r],:] @ W[e] ----------------
// BM=64 BN=128 BK=16, 256 threads, 4x8 per thread. grid=(NDIM/128, 3, NE)
template<int KDIM, int NDIM>
__global__ __launch_bounds__(256)
void moe_gemm_kernel(const float* __restrict__ X, const int* __restrict__ rowmap,
                     const float* __restrict__ W, float* __restrict__ C)
{
    __shared__ float As[16][64];
    __shared__ float Bs[16][128];
    const int tid = threadIdx.x;
    const int e  = blockIdx.z;
    const int by = blockIdx.y;
    const int bx = blockIdx.x;
    const float* We = W + (size_t)e*KDIM*NDIM;

    const int arow = tid >> 2;          // 0..63
    const int ac0  = (tid & 3) * 4;     // 0,4,8,12
    const int r0 = by*64 + arow;
    const int token = (r0 < CAP) ? rowmap[e*CAP + r0] : -1;
    const float* Ap = (token >= 0) ? (X + (size_t)token*KDIM + ac0) : (const float*)0;

    const int brow = tid >> 5;          // 0..7
    const int bcol = (tid & 31) * 4;    // 0..124
    const int trow = tid >> 4;          // 0..15
    const int tcol = tid & 15;          // 0..15

    float acc[4][8];
    #pragma unroll
    for (int i = 0; i < 4; i++)
        #pragma unroll
        for (int j = 0; j < 8; j++) acc[i][j] = 0.f;

    for (int k0 = 0; k0 < KDIM; k0 += 16) {
        float4 a4 = make_float4(0.f, 0.f, 0.f, 0.f);
        if (Ap) a4 = *(const float4*)(Ap + k0);
        As[ac0+0][arow] = a4.x; As[ac0+1][arow] = a4.y;
        As[ac0+2][arow] = a4.z; As[ac0+3][arow] = a4.w;
        float4 b0 = *(const float4*)(We + (size_t)(k0+brow  )*NDIM + bx*128 + bcol);
        float4 b1 = *(const float4*)(We + (size_t)(k0+brow+8)*NDIM + bx*128 + bcol);
        *(float4*)&Bs[brow  ][bcol] = b0;
        *(float4*)&Bs[brow+8][bcol] = b1;
        __syncthreads();
        #pragma unroll
        for (int kk = 0; kk < 16; kk++) {
            float4 ar  = *(const float4*)&As[kk][trow*4];
            float4 br0 = *(const float4*)&Bs[kk][tcol*8];
            float4 br1 = *(const float4*)&Bs[kk][tcol*8+4];
            float a_[4] = {ar.x, ar.y, ar.z, ar.w};
            float b_[8] = {br0.x,br0.y,br0.z,br0.w,br1.x,br1.y,br1.z,br1.w};
            #pragma unroll
            for (int i = 0; i < 4; i++)
                #pragma unroll
                for (int j = 0; j < 8; j++)
                    acc[i][j] = fmaf(a_[i], b_[j], acc[i][j]);
        }
        __syncthreads();
    }
    #pragma unroll
    for (int i = 0; i < 4; i++) {
        int r = by*64 + trow*4 + i;
        if (r < CAP) {
            float* Cp = C + ((size_t)e*CAP + r)*NDIM + bx*128 + tcol*8;
            *(float4*)(Cp)   = make_float4(acc[i][0], acc[i][1], acc[i][2], acc[i][3]);
            *(float4*)(Cp+4) = make_float4(acc[i][4], acc[i][5], acc[i][6], acc[i][7]);
        }
    }
}

// ---------------- attention: thread per query row, streaming 32-key tiles ----------------
__global__ __launch_bounds__(64)
void attn_kernel(const float* __restrict__ Q, const float* __restrict__ K,
                 const float* __restrict__ V, float* __restrict__ O)
{
    __shared__ float Ks[32][64];
    __shared__ float Vs[32][64];
    const int bh = blockIdx.y;
    const int b = bh / NH, h = bh % NH;
    const int qi = blockIdx.x*64 + threadIdx.x;
    const size_t qoff = ((size_t)(b*SEQ + qi))*DM + h*DKH;

    float qr[64];
    #pragma unroll
    for (int d = 0; d < 64; d += 4) {
        float4 t = *(const float4*)&Q[qoff + d];
        qr[d] = t.x*0.125f; qr[d+1] = t.y*0.125f; qr[d+2] = t.z*0.125f; qr[d+3] = t.w*0.125f;
    }
    float m = -1e30f, l = 0.f;
    float o[64];
    #pragma unroll
    for (int d = 0; d < 64; d++) o[d] = 0.f;

    const size_t kbase = ((size_t)b*SEQ)*DM + h*DKH;
    for (int kt = 0; kt < SEQ; kt += 32) {
        #pragma unroll
        for (int it = 0; it < 8; it++) {
            int f = threadIdx.x + it*64;         // float4 index 0..511
            int j = f >> 4; int d4 = (f & 15)*4;
            size_t src = kbase + (size_t)(kt + j)*DM + d4;
            *(float4*)&Ks[j][d4] = *(const float4*)&K[src];
            *(float4*)&Vs[j][d4] = *(const float4*)&V[src];
        }
        __syncthreads();
        float s[32];
        #pragma unroll
        for (int j = 0; j < 32; j++) {
            float acc = 0.f;
            #pragma unroll
            for (int d = 0; d < 64; d++) acc = fmaf(qr[d], Ks[j][d], acc);
            s[j] = acc;
        }
        float tmax = m;
        #pragma unroll
        for (int j = 0; j < 32; j++) tmax = fmaxf(tmax, s[j]);
        float f = expf(m - tmax);
        l *= f;
        #pragma unroll
        for (int d = 0; d < 64; d++) o[d] *= f;
        #pragma unroll
        for (int j = 0; j < 32; j++) {
            float p = expf(s[j] - tmax);
            l += p;
            #pragma unroll
            for (int d = 0; d < 64; d++) o[d] = fmaf(p, Vs[j][d], o[d]);
        }
        m = tmax;
        __syncthreads();
    }
    float inv = 1.f / l;
    #pragma unroll
    for (int d = 0; d < 64; d += 4) {
        float4 v = make_float4(o[d]*inv, o[d+1]*inv, o[d+2]*inv, o[d+3]*inv);
        *(float4*)&O[qoff + d] = v;
    }
}

// ---------------- layernorm over rows ----------------
__global__ void ln_kernel(const float* __restrict__ X, float* __restrict__ Y,
                          const float* __restrict__ gg, const float* __restrict__ bb, int len)
{
    __shared__ float sb[32];
    const int row = blockIdx.x;
    const float* xr = X + (size_t)row*len;
    float sum = 0.f;
    for (int c = threadIdx.x; c < len; c += blockDim.x) sum += xr[c];
    float mean = blk_sum(sum, sb) / len;
    float s2 = 0.f;
    for (int c = threadIdx.x; c < len; c += blockDim.x) { float d = xr[c]-mean; s2 += d*d; }
    float var = blk_sum(s2, sb) / len;
    float r = rsqrtf(var + EPSV);
    for (int c = threadIdx.x; c < len; c += blockDim.x)
        Y[(size_t)row*len + c] = (xr[c]-mean)*r*gg[c] + bb[c];
}

// ---------------- gating: logits + top-2 + normalized weights ----------------
__global__ void gate_kernel(const float* __restrict__ Xres, const float* __restrict__ wg, int grp)
{
    __shared__ float xr[DM];
    __shared__ float lg[NE];
    const int t = blockIdx.x;
    const int row = ((t >> 8) * SEQ) + grp*256 + (t & 255);
    for (int c = threadIdx.x; c < DM; c += blockDim.x) xr[c] = Xres[(size_t)row*DM + c];
    __syncthreads();
    if (threadIdx.x < NE) {
        float acc = 0.f;
        #pragma unroll 8
        for (int d = 0; d < DM; d++) acc = fmaf(xr[d], wg[d*NE + threadIdx.x], acc);
        lg[threadIdx.x] = acc;
    }
    __syncthreads();
    if (threadIdx.x == 0) {
        int i1 = 0; float v1 = lg[0];
        for (int e2 = 1; e2 < NE; e2++) if (lg[e2] > v1) { v1 = lg[e2]; i1 = e2; }
        int i2 = -1; float v2 = -1e30f;
        for (int e2 = 0; e2 < NE; e2++) if (e2 != i1 && lg[e2] > v2) { v2 = lg[e2]; i2 = e2; }
        float r2 = expf(v2 - v1);
        float inv = 1.f / (1.f + r2);
        g_e1[t] = i1; g_e2[t] = i2;
        g_wa[t] = inv; g_wb[t] = r2 * inv;
    }
}

// ---------------- GShard slot assignment: warp-per-expert ballot scan ----------------
__global__ void assign_kernel(int grp)
{
    __shared__ int scnt[NE];
    const int tid = threadIdx.x, lane = tid & 31, e = tid >> 5;   // 24 warps
    for (int i = tid; i < NE*CAP; i += blockDim.x) { g_rowg[i] = -1; g_rowl[i] = -1; }
    __syncthreads();
    // pass 1: top-1 choices (unmasked cumsum)
    int cnt = 0;
    for (int base = 0; base < TG; base += 32) {
        int t = base + lane;
        bool mm = (g_e1[t] == e);
        unsigned bal = __ballot_sync(0xffffffffu, mm);
        if (mm) {
            int loc = cnt + __popc(bal & ((1u << lane) - 1u));
            if (loc < CAP) {
                g_s1[t] = loc;
                int row = ((t >> 8) * SEQ) + grp*256 + (t & 255);
                g_rowg[e*CAP + loc] = row;
                g_rowl[e*CAP + loc] = t;
            } else g_s1[t] = -1;
        }
        cnt += __popc(bal);
    }
    if (lane == 0) scnt[e] = cnt;     // UNMASKED total (GShard offset)
    __syncthreads();
    // pass 2: top-2 choices, offset by total top-1 count
    cnt = scnt[e];
    for (int base = 0; base < TG; base += 32) {
        int t = base + lane;
        bool mm = (g_e2[t] == e);
        unsigned bal = __ballot_sync(0xffffffffu, mm);
        if (mm) {
            int loc = cnt + __popc(bal & ((1u << lane) - 1u));
            if (loc < CAP) {
                g_s2[t] = loc;
                int row = ((t >> 8) * SEQ) + grp*256 + (t & 255);
                g_rowg[e*CAP + loc] = row;
                g_rowl[e*CAP + loc] = t;
            } else g_s2[t] = -1;
        }
        cnt += __popc(bal);
    }
}

// ---------------- combine MoE1 + LN + relu ----------------
__global__ void combine1_kernel(const float* __restrict__ b1,
                                const float* __restrict__ lng, const float* __restrict__ lnb)
{
    __shared__ float sb[32];
    const int t = blockIdx.x;
    const int e1 = g_e1[t], e2 = g_e2[t], s1 = g_s1[t], s2 = g_s2[t];
    const float wa = g_wa[t], wb = g_wb[t];
    const float* p1 = (s1 >= 0) ? &g_sloth[((size_t)e1*CAP + s1)*DI] : (const float*)0;
    const float* p2 = (s2 >= 0) ? &g_sloth[((size_t)e2*CAP + s2)*DI] : (const float*)0;
    float vals[8];
    float sum = 0.f;
    #pragma unroll
    for (int i = 0; i < 8; i++) {
        int c = threadIdx.x + i*256;
        float hv = 0.f;
        if (p1) hv += wa * (p1[c] + b1[e1*DI + c]);
        if (p2) hv += wb * (p2[c] + b1[e2*DI + c]);
        vals[i] = hv; sum += hv;
    }
    float mean = blk_sum(sum, sb) / DI;
    float s2s = 0.f;
    #pragma unroll
    for (int i = 0; i < 8; i++) { float d = vals[i]-mean; s2s += d*d; }
    float var = blk_sum(s2s, sb) / DI;
    float r = rsqrtf(var + EPSV);
    #pragma unroll
    for (int i = 0; i < 8; i++) {
        int c = threadIdx.x + i*256;
        g_hpost[(size_t)t*DI + c] = fmaxf((vals[i]-mean)*r*lng[c] + lnb[c], 0.f);
    }
}

// ---------------- combine MoE2 + residual ----------------
__global__ void combine2_kernel(const float* __restrict__ b2, int grp)
{
    const int t = blockIdx.x;
    const int e1 = g_e1[t], e2 = g_e2[t], s1 = g_s1[t], s2 = g_s2[t];
    const float wa = g_wa[t], wb = g_wb[t];
    const int row = ((t >> 8) * SEQ) + grp*256 + (t & 255);
    #pragma unroll
    for (int i = 0; i < 4; i++) {
        int c = threadIdx.x + i*128;
        float y = 0.f;
        if (s1 >= 0) y += wa * (g_sloty[((size_t)e1*CAP + s1)*DM + c] + b2[e1*DM + c]);
        if (s2 >= 0) y += wb * (g_sloty[((size_t)e2*CAP + s2)*DM + c] + b2[e2*DM + c]);
        g_y[(size_t)row*DM + c] = y + g_res[(size_t)row*DM + c];
    }
}

// ---------------- launch ----------------
extern "C" void kernel_launch(void* const* d_in, const int* in_sizes, int n_in,
                              void* d_out, int out_size)
{
    // Classify inputs by (size, occurrence) — robust to dict-order vs signature-order.
    const float *x=0,*wq=0,*wk=0,*wv=0,*wo=0,*ln_attn_g=0,*ln_attn_b=0,*wg1=0,*w1=0,*b1=0,
                *w2=0,*b2=0,*ln_out_g=0,*ln_out_b=0;
    const float* ln2048[8] = {0,0,0,0,0,0,0,0};
    int c262=0,c512=0,c12k=0,c25m=0,c49k=0,c2k=0;
    for (int i = 0; i < n_in; i++) {
        const float* p = (const float*)d_in[i];
        switch (in_sizes[i]) {
            case 4194304: x = p; break;
            case 262144:
                if (c262==0) wq=p; else if (c262==1) wk=p; else if (c262==2) wv=p; else wo=p;
                c262++; break;
            case 512:
                if (c512==0) ln_attn_g=p; else if (c512==1) ln_attn_b=p;
                else if (c512==2) ln_out_g=p; else ln_out_b=p;
                c512++; break;
            case 12288:
                if (c12k==0) wg1=p; else b2=p;
                c12k++; break;
            case 25165824:
                if (c25m==0) w1=p; else w2=p;
                c25m++; break;
            case 49152:
                if (c49k==0) b1=p; /* second is wg2 (unused by reference) */
                c49k++; break;
            case 2048:
                if (c2k < 8) ln2048[c2k] = p;
                c2k++; break;
            default: break;
        }
    }

    float *p_q,*p_k,*p_v,*p_ctx,*p_tmp,*p_res,*p_y,*p_sloth,*p_sloty,*p_hpost;
    int *p_rowg,*p_rowl;
    cudaGetSymbolAddress((void**)&p_q,    g_q);
    cudaGetSymbolAddress((void**)&p_k,    g_k);
    cudaGetSymbolAddress((void**)&p_v,    g_v);
    cudaGetSymbolAddress((void**)&p_ctx,  g_ctx);
    cudaGetSymbolAddress((void**)&p_tmp,  g_tmp);
    cudaGetSymbolAddress((void**)&p_res,  g_res);
    cudaGetSymbolAddress((void**)&p_y,    g_y);
    cudaGetSymbolAddress((void**)&p_sloth,g_sloth);
    cudaGetSymbolAddress((void**)&p_sloty,g_sloty);
    cudaGetSymbolAddress((void**)&p_hpost,g_hpost);
    cudaGetSymbolAddress((void**)&p_rowg, g_rowg);
    cudaGetSymbolAddress((void**)&p_rowl, g_rowl);

    float* out = (float*)d_out;

    // 1) QKV projections
    dim3 gqkv(DM/128, NROWS/128);
    sgemm128<<<gqkv, 256>>>(x, wq, p_q, NROWS, DM, DM, (const float*)0, 0);
    sgemm128<<<gqkv, 256>>>(x, wk, p_k, NROWS, DM, DM, (const float*)0, 0);
    sgemm128<<<gqkv, 256>>>(x, wv, p_v, NROWS, DM, DM, (const float*)0, 0);

    // 2) attention
    attn_kernel<<<dim3(SEQ/64, NB*NH), 64>>>(p_q, p_k, p_v, p_ctx);

    // 3) output projection + relu + residual, then LN
    sgemm128<<<gqkv, 256>>>(p_ctx, wo, p_tmp, NROWS, DM, DM, x, 1);
    ln_kernel<<<NROWS, 256>>>(p_tmp, p_res, ln_attn_g, ln_attn_b, DM);

    // 4) TaskMoE per sequence group
    for (int grp = 0; grp < NGRP; grp++) {
        gate_kernel<<<TG, 128>>>(p_res, wg1, grp);
        assign_kernel<<<1, NE*32>>>(grp);
        moe_gemm_kernel<DM, DI><<<dim3(DI/128, 3, NE), 256>>>(p_res, p_rowg, w1, p_sloth);
        combine1_kernel<<<TG, 256>>>(b1, ln2048[2*grp], ln2048[2*grp+1]);
        moe_gemm_kernel<DI, DM><<<dim3(DM/128, 3, NE), 256>>>(p_hpost, p_rowl, w2, p_sloty);
        combine2_kernel<<<TG, 128>>>(b2, grp);
    }

    // 5) final LN
    ln_kernel<<<NROWS, 256>>>(p_y, out, ln_out_g, ln_out_b, DM);

    (void)out_size;
}

// round 4
// speedup vs baseline: 1.8770x; 1.8770x over previous
#include <cuda_runtime.h>
#include <cstdint>
#include <cstddef>

// ---------------- problem constants ----------------
#define NB    8
#define SEQ   1024
#define DM    512
#define NH    8
#define DI    2048
#define NE    24
#define CAP   171
#define TG    2048
#define NGRP  4
#define NROWS (NB*SEQ)      // 8192
#define NTOK  (NGRP*TG)     // 8192
#define SLOTS 768           // 4 groups * 192 (padded) slots per expert
#define GOFF  192           // slot offset per group
#define EPSV  1e-6f

// ---------------- device scratch ----------------
__device__ float g_q[NROWS*DM];
__device__ float g_k[NROWS*DM];
__device__ float g_v[NROWS*DM];
__device__ float g_ctx[NROWS*DM];
__device__ float g_tmp[NROWS*DM];
__device__ float g_res[NROWS*DM];     // post-attention LN (exact, for gating+residual)
__device__ float g_resr[NROWS*DM];    // tf32-rounded copy (GEMM1 input)
__device__ float g_y[NROWS*DM];
__device__ float g_wt1[(size_t)NE*DM*DI];   // rna(w1), original [e][k][n] layout
__device__ float g_wt2[(size_t)NE*DI*DM];   // rna(w2), original [e][k][n] layout
__device__ float g_sloth[(size_t)NE*SLOTS*DI];
__device__ float g_sloty[(size_t)NE*SLOTS*DM];
__device__ float g_hpost[(size_t)NTOK*DI];  // tf32-rounded (GEMM2 input)
__device__ int   g_e1[NTOK], g_e2[NTOK], g_s1[NTOK], g_s2[NTOK];
__device__ float g_wa[NTOK], g_wb[NTOK];
__device__ int   g_rowg[NE*SLOTS];    // -> global row in g_resr
__device__ int   g_rowl[NE*SLOTS];    // -> token id in g_hpost
__device__ const float* g_lnp[8];

// ---------------- PTX helpers ----------------
__device__ __forceinline__ float to_tf32(float x) {
    uint32_t u;
    asm("cvt.rna.tf32.f32 %0, %1;" : "=r"(u) : "f"(x));
    return __uint_as_float(u);
}
__device__ __forceinline__ uint32_t smem_cast(const void* p) {
    uint32_t a;
    asm("{ .reg .u64 t; cvta.to.shared.u64 t, %1; cvt.u32.u64 %0, t; }" : "=r"(a) : "l"(p));
    return a;
}
#define CP_ASYNC16(dst, src) \
    asm volatile("cp.async.cg.shared.global [%0], [%1], 16;" :: "r"(dst), "l"(src) : "memory")
#define CP_COMMIT() asm volatile("cp.async.commit_group;" ::: "memory")
#define CP_WAIT(n)  asm volatile("cp.async.wait_group %0;" :: "n"(n) : "memory")

__device__ __forceinline__ void mma_tf32(float* d, const uint32_t* a, const uint32_t* b) {
    asm volatile(
        "mma.sync.aligned.m16n8k8.row.col.f32.tf32.tf32.f32 "
        "{%0,%1,%2,%3}, {%4,%5,%6,%7}, {%8,%9}, {%0,%1,%2,%3};"
        : "+f"(d[0]), "+f"(d[1]), "+f"(d[2]), "+f"(d[3])
        : "r"(a[0]), "r"(a[1]), "r"(a[2]), "r"(a[3]), "r"(b[0]), "r"(b[1]));
}

// ---------------- block reduction ----------------
__device__ __forceinline__ float blk_sum(float v, float* sb) {
    int lane = threadIdx.x & 31, wid = threadIdx.x >> 5;
    #pragma unroll
    for (int o = 16; o; o >>= 1) v += __shfl_down_sync(0xffffffffu, v, o);
    if (lane == 0) sb[wid] = v;
    __syncthreads();
    int nw = (blockDim.x + 31) >> 5;
    if (wid == 0) {
        float r = (lane < nw) ? sb[lane] : 0.f;
        #pragma unroll
        for (int o = 16; o; o >>= 1) r += __shfl_down_sync(0xffffffffu, r, o);
        if (lane == 0) sb[0] = r;
    }
    __syncthreads();
    float r = sb[0];
    __syncthreads();
    return r;
}

// ---------------- elementwise tf32 rounding copy ----------------
__global__ void round_copy(const float* __restrict__ src, float* __restrict__ dst)
{
    size_t i = ((size_t)blockIdx.x * blockDim.x + threadIdx.x) * 4;
    float4 v = *(const float4*)(src + i);
    v.x = to_tf32(v.x); v.y = to_tf32(v.y); v.z = to_tf32(v.z); v.w = to_tf32(v.w);
    *(float4*)(dst + i) = v;
}

// ---------------- dense fp32 SGEMM (128x128x8) ----------------
__global__ __launch_bounds__(256)
void sgemm128(const float* __restrict__ A, const float* __restrict__ B,
              float* __restrict__ C, int M, int N, int K,
              const float* __restrict__ R, int epi)
{
    __shared__ float As[8][128];
    __shared__ float Bs[8][128];
    const int tid = threadIdx.x;
    const int bx = blockIdx.x, by = blockIdx.y;
    const int trow = tid >> 4, tcol = tid & 15;

    float acc[8][8];
    #pragma unroll
    for (int i = 0; i < 8; i++)
        #pragma unroll
        for (int j = 0; j < 8; j++) acc[i][j] = 0.f;

    const int aRow = tid >> 1, aCol = (tid & 1) * 4;
    const int bRow = tid >> 5, bCol = (tid & 31) * 4;
    const float* Ap = A + (size_t)(by*128 + aRow)*K + aCol;
    const float* Bp = B + (size_t)bRow*N + bx*128 + bCol;

    for (int k0 = 0; k0 < K; k0 += 8) {
        float4 a4 = *(const float4*)(Ap + k0);
        float4 b4 = *(const float4*)(Bp + (size_t)k0*N);
        As[aCol+0][aRow] = a4.x; As[aCol+1][aRow] = a4.y;
        As[aCol+2][aRow] = a4.z; As[aCol+3][aRow] = a4.w;
        *(float4*)&Bs[bRow][bCol] = b4;
        __syncthreads();
        #pragma unroll
        for (int kk = 0; kk < 8; kk++) {
            float4 ar0 = *(const float4*)&As[kk][trow*8];
            float4 ar1 = *(const float4*)&As[kk][trow*8+4];
            float4 br0 = *(const float4*)&Bs[kk][tcol*8];
            float4 br1 = *(const float4*)&Bs[kk][tcol*8+4];
            float a_[8] = {ar0.x,ar0.y,ar0.z,ar0.w,ar1.x,ar1.y,ar1.z,ar1.w};
            float b_[8] = {br0.x,br0.y,br0.z,br0.w,br1.x,br1.y,br1.z,br1.w};
            #pragma unroll
            for (int i = 0; i < 8; i++)
                #pragma unroll
                for (int j = 0; j < 8; j++)
                    acc[i][j] = fmaf(a_[i], b_[j], acc[i][j]);
        }
        __syncthreads();
    }
    #pragma unroll
    for (int i = 0; i < 8; i++) {
        int row = by*128 + trow*8 + i;
        #pragma unroll
        for (int j = 0; j < 8; j += 4) {
            int col = bx*128 + tcol*8 + j;
            float4 v = make_float4(acc[i][j], acc[i][j+1], acc[i][j+2], acc[i][j+3]);
            if (epi == 1) {
                const float4 r = *(const float4*)&R[(size_t)row*N + col];
                v.x = fmaxf(v.x, 0.f) + r.x;
                v.y = fmaxf(v.y, 0.f) + r.y;
                v.z = fmaxf(v.z, 0.f) + r.z;
                v.w = fmaxf(v.w, 0.f) + r.w;
            }
            *(float4*)&C[(size_t)row*N + col] = v;
        }
    }
}

// ---------------- MoE grouped GEMM via mma.sync tf32 (HMMA) ----------------
// C[e*SLOTS+m, n0+n] = sum_k X[rowmap[e*SLOTS+m], k] * W[e][k][n]
// BM=128, BN=128, BK=32. 256 threads = 4(M) x 2(N) warps, warp tile 32x64.
// Smem: A row-major [128 m][32 k] pitch 36; B k-major [32 k][128 n] pitch 136.
#define AP 36
#define BP 136
#define ABUF (128*AP)           // floats per A buffer (4608)
#define BBUF (32*BP)            // floats per B buffer (4352)
#define MOE_SMEM_BYTES ((2*ABUF + 2*BBUF) * 4)   // 71680

template<int KDIM, int NDIM>
__global__ __launch_bounds__(256)
void moe_hmma(const float* __restrict__ X, const int* __restrict__ rowmap,
              const float* __restrict__ W, float* __restrict__ C)
{
    constexpr int NC = KDIM / 32;
    extern __shared__ float sm[];
    float* Abuf = sm;                 // [2][ABUF]
    float* Bbuf = sm + 2*ABUF;        // [2][BBUF]

    const int tid = threadIdx.x;
    const int wid = tid >> 5, lane = tid & 31;
    const int wm = wid & 3, wn = wid >> 2;        // 4 x 2 warp grid
    const int m0w = wm*32, n0w = wn*64;
    const int r = lane >> 2, cq = lane & 3;

    const int e  = blockIdx.z;
    const int mt = blockIdx.y;
    const int n0 = blockIdx.x * 128;

    // ---- load setup ----
    const int rowA = tid >> 1, halfA = tid & 1;   // 128 rows, 2 threads/row
    int token = rowmap[e*SLOTS + mt*128 + rowA];
    if (token < 0) token = 0;
    const float* srcA = X + (size_t)token * KDIM + halfA*16;
    const uint32_t smA = smem_cast(Abuf) + (uint32_t)(rowA*AP + halfA*16)*4;

    const int rowB = tid >> 3, segB = tid & 7;    // 32 k-rows, 8 threads/row
    const float* srcB = W + (size_t)e*KDIM*NDIM + (size_t)rowB*NDIM + n0 + segB*16;
    const uint32_t smB = smem_cast(Bbuf) + (uint32_t)(rowB*BP + segB*16)*4;

    float acc[2][8][4];
    #pragma unroll
    for (int mi = 0; mi < 2; mi++)
        #pragma unroll
        for (int ni = 0; ni < 8; ni++)
            #pragma unroll
            for (int q = 0; q < 4; q++) acc[mi][ni][q] = 0.f;

    auto load_chunk = [&](int c) {
        uint32_t da = smA + (uint32_t)(c & 1)*(ABUF*4);
        const float* sa = srcA + c*32;
        #pragma unroll
        for (int i = 0; i < 4; i++) CP_ASYNC16(da + i*16, sa + i*4);
        uint32_t db = smB + (uint32_t)(c & 1)*(BBUF*4);
        const float* sb2 = srcB + (size_t)c*32*NDIM;
        #pragma unroll
        for (int i = 0; i < 4; i++) CP_ASYNC16(db + i*16, sb2 + i*4);
        CP_COMMIT();
    };

    load_chunk(0);
    for (int c = 0; c < NC; c++) {
        if (c + 1 < NC) { load_chunk(c + 1); CP_WAIT(1); }
        else           { CP_WAIT(0); }
        __syncthreads();

        const float* As_ = Abuf + (c & 1)*ABUF;
        const float* Bs_ = Bbuf + (c & 1)*BBUF;
        #pragma unroll
        for (int ks = 0; ks < 4; ks++) {
            uint32_t a[2][4];
            #pragma unroll
            for (int mi = 0; mi < 2; mi++) {
                int m = m0w + mi*16 + r;
                a[mi][0] = __float_as_uint(As_[m*AP     + ks*8 + cq]);
                a[mi][1] = __float_as_uint(As_[(m+8)*AP + ks*8 + cq]);
                a[mi][2] = __float_as_uint(As_[m*AP     + ks*8 + cq + 4]);
                a[mi][3] = __float_as_uint(As_[(m+8)*AP + ks*8 + cq + 4]);
            }
            uint32_t b[8][2];
            #pragma unroll
            for (int ni = 0; ni < 8; ni++) {
                int n = n0w + ni*8 + r;
                b[ni][0] = __float_as_uint(Bs_[(ks*8 + cq    )*BP + n]);
                b[ni][1] = __float_as_uint(Bs_[(ks*8 + cq + 4)*BP + n]);
            }
            #pragma unroll
            for (int mi = 0; mi < 2; mi++)
                #pragma unroll
                for (int ni = 0; ni < 8; ni++)
                    mma_tf32(acc[mi][ni], a[mi], b[ni]);
        }
        __syncthreads();
    }

    // ---- epilogue ----
    #pragma unroll
    for (int mi = 0; mi < 2; mi++) {
        int mrow = mt*128 + m0w + mi*16 + r;
        float* C0 = C + ((size_t)e*SLOTS + mrow    )*NDIM + n0 + n0w;
        float* C1 = C + ((size_t)e*SLOTS + mrow + 8)*NDIM + n0 + n0w;
        #pragma unroll
        for (int ni = 0; ni < 8; ni++) {
            int col = ni*8 + 2*cq;
            *(float2*)(C0 + col) = make_float2(acc[mi][ni][0], acc[mi][ni][1]);
            *(float2*)(C1 + col) = make_float2(acc[mi][ni][2], acc[mi][ni][3]);
        }
    }
}

// ---------------- attention (fp32, float4 smem reads) ----------------
__global__ __launch_bounds__(64)
void attn_kernel(const float* __restrict__ Q, const float* __restrict__ K,
                 const float* __restrict__ V, float* __restrict__ O)
{
    __shared__ float Ks[32][64];
    __shared__ float Vs[32][64];
    const int bh = blockIdx.y;
    const int b = bh / NH, h = bh % NH;
    const int qi = blockIdx.x*64 + threadIdx.x;
    const size_t qoff = ((size_t)(b*SEQ + qi))*DM + h*64;

    float qr[64];
    #pragma unroll
    for (int d = 0; d < 64; d += 4) {
        float4 t = *(const float4*)&Q[qoff + d];
        qr[d] = t.x*0.125f; qr[d+1] = t.y*0.125f; qr[d+2] = t.z*0.125f; qr[d+3] = t.w*0.125f;
    }
    float m = -1e30f, l = 0.f;
    float o[64];
    #pragma unroll
    for (int d = 0; d < 64; d++) o[d] = 0.f;

    const size_t kbase = ((size_t)b*SEQ)*DM + h*64;
    for (int kt = 0; kt < SEQ; kt += 32) {
        #pragma unroll
        for (int it = 0; it < 8; it++) {
            int f = threadIdx.x + it*64;
            int j = f >> 4; int d4 = (f & 15)*4;
            size_t src = kbase + (size_t)(kt + j)*DM + d4;
            *(float4*)&Ks[j][d4] = *(const float4*)&K[src];
            *(float4*)&Vs[j][d4] = *(const float4*)&V[src];
        }
        __syncthreads();
        float s[32];
        #pragma unroll
        for (int j = 0; j < 32; j++) {
            float a0 = 0.f, a1 = 0.f, a2 = 0.f, a3 = 0.f;
            #pragma unroll
            for (int d4 = 0; d4 < 16; d4++) {
                float4 kv = *(const float4*)&Ks[j][d4*4];
                a0 = fmaf(qr[d4*4+0], kv.x, a0);
                a1 = fmaf(qr[d4*4+1], kv.y, a1);
                a2 = fmaf(qr[d4*4+2], kv.z, a2);
                a3 = fmaf(qr[d4*4+3], kv.w, a3);
            }
            s[j] = (a0 + a1) + (a2 + a3);
        }
        float tmax = m;
        #pragma unroll
        for (int j = 0; j < 32; j++) tmax = fmaxf(tmax, s[j]);
        float f = expf(m - tmax);
        l *= f;
        #pragma unroll
        for (int d = 0; d < 64; d++) o[d] *= f;
        #pragma unroll
        for (int j = 0; j < 32; j++) {
            float p = expf(s[j] - tmax);
            l += p;
            #pragma unroll
            for (int d4 = 0; d4 < 16; d4++) {
                float4 vv = *(const float4*)&Vs[j][d4*4];
                o[d4*4+0] = fmaf(p, vv.x, o[d4*4+0]);
                o[d4*4+1] = fmaf(p, vv.y, o[d4*4+1]);
                o[d4*4+2] = fmaf(p, vv.z, o[d4*4+2]);
                o[d4*4+3] = fmaf(p, vv.w, o[d4*4+3]);
            }
        }
        m = tmax;
        __syncthreads();
    }
    float inv = 1.f / l;
    #pragma unroll
    for (int d = 0; d < 64; d += 4) {
        *(float4*)&O[qoff + d] = make_float4(o[d]*inv, o[d+1]*inv, o[d+2]*inv, o[d+3]*inv);
    }
}

// ---------------- layernorm (optional tf32-rounded second output) ----------------
__global__ void ln_kernel(const float* __restrict__ X, float* __restrict__ Y,
                          float* __restrict__ Yr,
                          const float* __restrict__ gg, const float* __restrict__ bb, int len)
{
    __shared__ float sb[32];
    const int row = blockIdx.x;
    const float* xr = X + (size_t)row*len;
    float sum = 0.f;
    for (int c = threadIdx.x; c < len; c += blockDim.x) sum += xr[c];
    float mean = blk_sum(sum, sb) / len;
    float s2 = 0.f;
    for (int c = threadIdx.x; c < len; c += blockDim.x) { float d = xr[c]-mean; s2 += d*d; }
    float var = blk_sum(s2, sb) / len;
    float r = rsqrtf(var + EPSV);
    for (int c = threadIdx.x; c < len; c += blockDim.x) {
        float v = (xr[c]-mean)*r*gg[c] + bb[c];
        Y[(size_t)row*len + c] = v;
        if (Yr) Yr[(size_t)row*len + c] = to_tf32(v);
    }
}

// ---------------- gating (fp32 exact) ----------------
__global__ void gate_kernel(const float* __restrict__ Xres, const float* __restrict__ wg)
{
    __shared__ float xr[DM];
    __shared__ float lg[NE];
    const int tt = blockIdx.x;                 // 0..8191
    const int grp = tt >> 11, ti = tt & 2047;
    const int row = ((ti >> 8) * SEQ) + grp*256 + (ti & 255);
    for (int c = threadIdx.x; c < DM; c += blockDim.x) xr[c] = Xres[(size_t)row*DM + c];
    __syncthreads();
    if (threadIdx.x < NE) {
        float acc = 0.f;
        #pragma unroll 8
        for (int d = 0; d < DM; d++) acc = fmaf(xr[d], wg[d*NE + threadIdx.x], acc);
        lg[threadIdx.x] = acc;
    }
    __syncthreads();
    if (threadIdx.x == 0) {
        int i1 = 0; float v1 = lg[0];
        for (int e2 = 1; e2 < NE; e2++) if (lg[e2] > v1) { v1 = lg[e2]; i1 = e2; }
        int i2 = -1; float v2 = -1e30f;
        for (int e2 = 0; e2 < NE; e2++) if (e2 != i1 && lg[e2] > v2) { v2 = lg[e2]; i2 = e2; }
        float r2 = expf(v2 - v1);
        float inv = 1.f / (1.f + r2);
        g_e1[tt] = i1; g_e2[tt] = i2;
        g_wa[tt] = inv; g_wb[tt] = r2 * inv;
    }
}

// ---------------- GShard slot assignment (one block per group) ----------------
__global__ void assign_kernel()
{
    __shared__ int scnt[NE];
    const int grp = blockIdx.x;
    const int tid = threadIdx.x, lane = tid & 31, e = tid >> 5;   // 24 warps
    for (int i = tid; i < NE*GOFF; i += blockDim.x) {
        int ee = i / GOFF, s = i % GOFF;
        g_rowg[ee*SLOTS + grp*GOFF + s] = -1;
        g_rowl[ee*SLOTS + grp*GOFF + s] = -1;
    }
    __syncthreads();
    int cnt = 0;
    for (int base = 0; base < TG; base += 32) {
        int ti = base + lane;
        int tt = grp*TG + ti;
        bool mm = (g_e1[tt] == e);
        unsigned bal = __ballot_sync(0xffffffffu, mm);
        if (mm) {
            int loc = cnt + __popc(bal & ((1u << lane) - 1u));
            if (loc < CAP) {
                int srow = grp*GOFF + loc;
                g_s1[tt] = srow;
                int row = ((ti >> 8) * SEQ) + grp*256 + (ti & 255);
                g_rowg[e*SLOTS + srow] = row;
                g_rowl[e*SLOTS + srow] = tt;
            } else g_s1[tt] = -1;
        }
        cnt += __popc(bal);
    }
    if (lane == 0) scnt[e] = cnt;            // unmasked total (GShard offset)
    __syncthreads();
    cnt = scnt[e];
    for (int base = 0; base < TG; base += 32) {
        int ti = base + lane;
        int tt = grp*TG + ti;
        bool mm = (g_e2[tt] == e);
        unsigned bal = __ballot_sync(0xffffffffu, mm);
        if (mm) {
            int loc = cnt + __popc(bal & ((1u << lane) - 1u));
            if (loc < CAP) {
                int srow = grp*GOFF + loc;
                g_s2[tt] = srow;
                int row = ((ti >> 8) * SEQ) + grp*256 + (ti & 255);
                g_rowg[e*SLOTS + srow] = row;
                g_rowl[e*SLOTS + srow] = tt;
            } else g_s2[tt] = -1;
        }
        cnt += __popc(bal);
    }
}

// ---------------- combine MoE1 + bias + LN + relu + tf32 round ----------------
__global__ void combine1_kernel(const float* __restrict__ b1)
{
    __shared__ float sb[32];
    const int tt = blockIdx.x;
    const int grp = tt >> 11;
    const float* lng = g_lnp[2*grp];
    const float* lnb = g_lnp[2*grp+1];
    const int e1 = g_e1[tt], e2 = g_e2[tt], s1 = g_s1[tt], s2 = g_s2[tt];
    const float wa = g_wa[tt], wb = g_wb[tt];
    const float* p1 = (s1 >= 0) ? &g_sloth[((size_t)e1*SLOTS + s1)*DI] : (const float*)0;
    const float* p2 = (s2 >= 0) ? &g_sloth[((size_t)e2*SLOTS + s2)*DI] : (const float*)0;
    float vals[8];
    float sum = 0.f;
    #pragma unroll
    for (int i = 0; i < 8; i++) {
        int c = threadIdx.x + i*256;
        float hv = 0.f;
        if (p1) hv += wa * (p1[c] + b1[e1*DI + c]);
        if (p2) hv += wb * (p2[c] + b1[e2*DI + c]);
        vals[i] = hv; sum += hv;
    }
    float mean = blk_sum(sum, sb) / DI;
    float s2s = 0.f;
    #pragma unroll
    for (int i = 0; i < 8; i++) { float d = vals[i]-mean; s2s += d*d; }
    float var = blk_sum(s2s, sb) / DI;
    float r = rsqrtf(var + EPSV);
    #pragma unroll
    for (int i = 0; i < 8; i++) {
        int c = threadIdx.x + i*256;
        float v = fmaxf((vals[i]-mean)*r*lng[c] + lnb[c], 0.f);
        g_hpost[(size_t)tt*DI + c] = to_tf32(v);
    }
}

// ---------------- combine MoE2 + bias + residual ----------------
__global__ void combine2_kernel(const float* __restrict__ b2)
{
    const int tt = blockIdx.x;
    const int grp = tt >> 11, ti = tt & 2047;
    const int e1 = g_e1[tt], e2 = g_e2[tt], s1 = g_s1[tt], s2 = g_s2[tt];
    const float wa = g_wa[tt], wb = g_wb[tt];
    const int row = ((ti >> 8) * SEQ) + grp*256 + (ti & 255);
    #pragma unroll
    for (int i = 0; i < 4; i++) {
        int c = threadIdx.x + i*128;
        float y = 0.f;
        if (s1 >= 0) y += wa * (g_sloty[((size_t)e1*SLOTS + s1)*DM + c] + b2[e1*DM + c]);
        if (s2 >= 0) y += wb * (g_sloty[((size_t)e2*SLOTS + s2)*DM + c] + b2[e2*DM + c]);
        g_y[(size_t)row*DM + c] = y + g_res[(size_t)row*DM + c];
    }
}

__global__ void set_lnp_kernel(const float* a0, const float* a1, const float* a2, const float* a3,
                               const float* a4, const float* a5, const float* a6, const float* a7)
{
    g_lnp[0]=a0; g_lnp[1]=a1; g_lnp[2]=a2; g_lnp[3]=a3;
    g_lnp[4]=a4; g_lnp[5]=a5; g_lnp[6]=a6; g_lnp[7]=a7;
}

// ---------------- launch ----------------
extern "C" void kernel_launch(void* const* d_in, const int* in_sizes, int n_in,
                              void* d_out, int out_size)
{
    const float *x=0,*wq=0,*wk=0,*wv=0,*wo=0,*ln_attn_g=0,*ln_attn_b=0,*wg1=0,*w1=0,*b1=0,
                *w2=0,*b2=0,*ln_out_g=0,*ln_out_b=0;
    const float* ln2048[8] = {0,0,0,0,0,0,0,0};
    int c262=0,c512=0,c12k=0,c25m=0,c49k=0,c2k=0;
    for (int i = 0; i < n_in; i++) {
        const float* p = (const float*)d_in[i];
        switch (in_sizes[i]) {
            case 4194304: x = p; break;
            case 262144:
                if (c262==0) wq=p; else if (c262==1) wk=p; else if (c262==2) wv=p; else wo=p;
                c262++; break;
            case 512:
                if (c512==0) ln_attn_g=p; else if (c512==1) ln_attn_b=p;
                else if (c512==2) ln_out_g=p; else ln_out_b=p;
                c512++; break;
            case 12288:
                if (c12k==0) wg1=p; else b2=p;
                c12k++; break;
            case 25165824:
                if (c25m==0) w1=p; else w2=p;
                c25m++; break;
            case 49152:
                if (c49k==0) b1=p;
                c49k++; break;
            case 2048:
                if (c2k < 8) ln2048[c2k] = p;
                c2k++; break;
            default: break;
        }
    }

    float *p_q,*p_k,*p_v,*p_ctx,*p_tmp,*p_res,*p_resr,*p_y,*p_wt1,*p_wt2,*p_sloth,*p_sloty,*p_hpost;
    int *p_rowg,*p_rowl;
    cudaGetSymbolAddress((void**)&p_q,     g_q);
    cudaGetSymbolAddress((void**)&p_k,     g_k);
    cudaGetSymbolAddress((void**)&p_v,     g_v);
    cudaGetSymbolAddress((void**)&p_ctx,   g_ctx);
    cudaGetSymbolAddress((void**)&p_tmp,   g_tmp);
    cudaGetSymbolAddress((void**)&p_res,   g_res);
    cudaGetSymbolAddress((void**)&p_resr,  g_resr);
    cudaGetSymbolAddress((void**)&p_y,     g_y);
    cudaGetSymbolAddress((void**)&p_wt1,   g_wt1);
    cudaGetSymbolAddress((void**)&p_wt2,   g_wt2);
    cudaGetSymbolAddress((void**)&p_sloth, g_sloth);
    cudaGetSymbolAddress((void**)&p_sloty, g_sloty);
    cudaGetSymbolAddress((void**)&p_hpost, g_hpost);
    cudaGetSymbolAddress((void**)&p_rowg,  g_rowg);
    cudaGetSymbolAddress((void**)&p_rowl,  g_rowl);

    float* out = (float*)d_out;

    cudaFuncSetAttribute(moe_hmma<DM, DI>, cudaFuncAttributeMaxDynamicSharedMemorySize, MOE_SMEM_BYTES);
    cudaFuncSetAttribute(moe_hmma<DI, DM>, cudaFuncAttributeMaxDynamicSharedMemorySize, MOE_SMEM_BYTES);

    // 0) weight tf32 pre-rounding (elementwise, layout preserved) + LN param table
    {
        size_t nw = (size_t)NE*DM*DI;   // 25,165,824
        int blocks = (int)(nw / (256*4));
        round_copy<<<blocks, 256>>>(w1, p_wt1);
        round_copy<<<blocks, 256>>>(w2, p_wt2);
    }
    set_lnp_kernel<<<1,1>>>(ln2048[0],ln2048[1],ln2048[2],ln2048[3],
                            ln2048[4],ln2048[5],ln2048[6],ln2048[7]);

    // 1) QKV projections (fp32)
    dim3 gqkv(DM/128, NROWS/128);
    sgemm128<<<gqkv, 256>>>(x, wq, p_q, NROWS, DM, DM, (const float*)0, 0);
    sgemm128<<<gqkv, 256>>>(x, wk, p_k, NROWS, DM, DM, (const float*)0, 0);
    sgemm128<<<gqkv, 256>>>(x, wv, p_v, NROWS, DM, DM, (const float*)0, 0);

    // 2) attention (fp32)
    attn_kernel<<<dim3(SEQ/64, NB*NH), 64>>>(p_q, p_k, p_v, p_ctx);

    // 3) output projection + relu + residual, then LN (exact + tf32 copy)
    sgemm128<<<gqkv, 256>>>(p_ctx, wo, p_tmp, NROWS, DM, DM, x, 1);
    ln_kernel<<<NROWS, 256>>>(p_tmp, p_res, p_resr, ln_attn_g, ln_attn_b, DM);

    // 4) routing (all 4 groups)
    gate_kernel<<<NTOK, 128>>>(p_res, wg1);
    assign_kernel<<<NGRP, NE*32>>>();

    // 5) MoE GEMM1 (HMMA tf32), combine, GEMM2, combine
    moe_hmma<DM, DI><<<dim3(DI/128, SLOTS/128, NE), 256, MOE_SMEM_BYTES>>>(p_resr, p_rowg, p_wt1, p_sloth);
    combine1_kernel<<<NTOK, 256>>>(b1);
    moe_hmma<DI, DM><<<dim3(DM/128, SLOTS/128, NE), 256, MOE_SMEM_BYTES>>>(p_hpost, p_rowl, p_wt2, p_sloty);
    combine2_kernel<<<NTOK, 128>>>(b2);

    // 6) final LN
    ln_kernel<<<NROWS, 256>>>(p_y, out, (float*)0, ln_out_g, ln_out_b, DM);

    (void)out_size;
}

// round 5
// speedup vs baseline: 2.4780x; 1.3202x over previous
#include <cuda_runtime.h>
#include <cuda_fp16.h>
#include <cstdint>
#include <cstddef>

// ---------------- problem constants ----------------
#define NB    8
#define SEQ   1024
#define DM    512
#define NH    8
#define DI    2048
#define NE    24
#define CAP   171
#define TG    2048
#define NGRP  4
#define NROWS (NB*SEQ)      // 8192
#define NTOK  (NGRP*TG)     // 8192
#define SLOTS 768           // 4 groups * 192 (padded) slots per expert
#define GOFF  192
#define EPSV  1e-6f

// ---------------- device scratch ----------------
__device__ float  g_q[NROWS*DM];
__device__ float  g_k[NROWS*DM];
__device__ float  g_v[NROWS*DM];
__device__ float  g_ctx[NROWS*DM];
__device__ float  g_tmp[NROWS*DM];
__device__ float  g_res[NROWS*DM];     // post-attention LN (exact: gating + residual)
__device__ __half g_resh[NROWS*DM];    // fp16 copy (MoE GEMM1 input)
__device__ float  g_y[NROWS*DM];
__device__ __half g_wh1[(size_t)NE*DI*DM];   // w1 as half, transposed [e][n=DI][k=DM]
__device__ __half g_wh2[(size_t)NE*DM*DI];   // w2 as half, transposed [e][n=DM][k=DI]
__device__ float  g_sloth[(size_t)NE*SLOTS*DI];
__device__ float  g_sloty[(size_t)NE*SLOTS*DM];
__device__ __half g_hpost[(size_t)NTOK*DI];  // fp16 (MoE GEMM2 input)
__device__ int    g_e1[NTOK], g_e2[NTOK], g_s1[NTOK], g_s2[NTOK];
__device__ float  g_wa[NTOK], g_wb[NTOK];
__device__ int    g_rowg[NE*SLOTS];
__device__ int    g_rowl[NE*SLOTS];
__device__ const float* g_lnp[8];

// ---------------- PTX helpers ----------------
__device__ __forceinline__ uint32_t smem_cast(const void* p) {
    uint32_t a;
    asm("{ .reg .u64 t; cvta.to.shared.u64 t, %1; cvt.u32.u64 %0, t; }" : "=r"(a) : "l"(p));
    return a;
}
#define CP_ASYNC16(dst, src) \
    asm volatile("cp.async.cg.shared.global [%0], [%1], 16;" :: "r"(dst), "l"(src) : "memory")
#define CP_COMMIT() asm volatile("cp.async.commit_group;" ::: "memory")
#define CP_WAIT(n)  asm volatile("cp.async.wait_group %0;" :: "n"(n) : "memory")

__device__ __forceinline__ void mma_f16(float* d, const uint32_t* a, const uint32_t* b) {
    asm volatile(
        "mma.sync.aligned.m16n8k16.row.col.f32.f16.f16.f32 "
        "{%0,%1,%2,%3}, {%4,%5,%6,%7}, {%8,%9}, {%0,%1,%2,%3};"
        : "+f"(d[0]), "+f"(d[1]), "+f"(d[2]), "+f"(d[3])
        : "r"(a[0]), "r"(a[1]), "r"(a[2]), "r"(a[3]), "r"(b[0]), "r"(b[1]));
}

// ---------------- block reduction ----------------
__device__ __forceinline__ float blk_sum(float v, float* sb) {
    int lane = threadIdx.x & 31, wid = threadIdx.x >> 5;
    #pragma unroll
    for (int o = 16; o; o >>= 1) v += __shfl_down_sync(0xffffffffu, v, o);
    if (lane == 0) sb[wid] = v;
    __syncthreads();
    int nw = (blockDim.x + 31) >> 5;
    if (wid == 0) {
        float r = (lane < nw) ? sb[lane] : 0.f;
        #pragma unroll
        for (int o = 16; o; o >>= 1) r += __shfl_down_sync(0xffffffffu, r, o);
        if (lane == 0) sb[0] = r;
    }
    __syncthreads();
    float r = sb[0];
    __syncthreads();
    return r;
}

// ---------------- weight prep: W[e][k][n] float -> Wh[e][n][k] half ----------------
__global__ void transpose_half(const float* __restrict__ W, __half* __restrict__ Wh,
                               int K, int N)
{
    __shared__ float t[32][33];
    const int e = blockIdx.z;
    const int n0 = blockIdx.x * 32, k0 = blockIdx.y * 32;
    const float* We = W + (size_t)e * K * N;
    __half* Whe = Wh + (size_t)e * K * N;
    const int tx = threadIdx.x, ty = threadIdx.y;   // 32 x 8
    #pragma unroll
    for (int i = 0; i < 32; i += 8)
        t[ty + i][tx] = We[(size_t)(k0 + ty + i) * N + n0 + tx];
    __syncthreads();
    #pragma unroll
    for (int i = 0; i < 32; i += 8)
        Whe[(size_t)(n0 + ty + i) * K + k0 + tx] = __float2half_rn(t[tx][ty + i]);
}

// ---------------- dense fp32 SGEMM (128x128x8), conflict-free LDS ----------------
__global__ __launch_bounds__(256)
void sgemm128(const float* __restrict__ A, const float* __restrict__ B,
              float* __restrict__ C, int M, int N, int K,
              const float* __restrict__ R, int epi)
{
    __shared__ float As[8][128];
    __shared__ float Bs[8][128];
    const int tid = threadIdx.x;
    const int bx = blockIdx.x, by = blockIdx.y;
    const int trow = tid >> 4, tcol = tid & 15;

    float acc[8][8];
    #pragma unroll
    for (int i = 0; i < 8; i++)
        #pragma unroll
        for (int j = 0; j < 8; j++) acc[i][j] = 0.f;

    const int aRow = tid >> 1, aCol = (tid & 1) * 4;
    const int bRow = tid >> 5, bCol = (tid & 31) * 4;
    const float* Ap = A + (size_t)(by*128 + aRow)*K + aCol;
    const float* Bp = B + (size_t)bRow*N + bx*128 + bCol;

    for (int k0 = 0; k0 < K; k0 += 8) {
        float4 a4 = *(const float4*)(Ap + k0);
        float4 b4 = *(const float4*)(Bp + (size_t)k0*N);
        As[aCol+0][aRow] = a4.x; As[aCol+1][aRow] = a4.y;
        As[aCol+2][aRow] = a4.z; As[aCol+3][aRow] = a4.w;
        *(float4*)&Bs[bRow][bCol] = b4;
        __syncthreads();
        #pragma unroll
        for (int kk = 0; kk < 8; kk++) {
            float4 ar0 = *(const float4*)&As[kk][trow*8];
            float4 ar1 = *(const float4*)&As[kk][trow*8+4];
            float4 br0 = *(const float4*)&Bs[kk][tcol*4];        // conflict-free: quarter-warp
            float4 br1 = *(const float4*)&Bs[kk][tcol*4+64];     // lanes cover one 128B line
            float a_[8] = {ar0.x,ar0.y,ar0.z,ar0.w,ar1.x,ar1.y,ar1.z,ar1.w};
            float b_[8] = {br0.x,br0.y,br0.z,br0.w,br1.x,br1.y,br1.z,br1.w};
            #pragma unroll
            for (int i = 0; i < 8; i++)
                #pragma unroll
                for (int j = 0; j < 8; j++)
                    acc[i][j] = fmaf(a_[i], b_[j], acc[i][j]);
        }
        __syncthreads();
    }
    #pragma unroll
    for (int i = 0; i < 8; i++) {
        int row = by*128 + trow*8 + i;
        #pragma unroll
        for (int g = 0; g < 2; g++) {
            int col = bx*128 + tcol*4 + g*64;
            float4 v = make_float4(acc[i][g*4], acc[i][g*4+1], acc[i][g*4+2], acc[i][g*4+3]);
            if (epi == 1) {
                const float4 r = *(const float4*)&R[(size_t)row*N + col];
                v.x = fmaxf(v.x, 0.f) + r.x;
                v.y = fmaxf(v.y, 0.f) + r.y;
                v.z = fmaxf(v.z, 0.f) + r.z;
                v.w = fmaxf(v.w, 0.f) + r.w;
            }
            *(float4*)&C[(size_t)row*N + col] = v;
        }
    }
}

// ---------------- MoE grouped GEMM via mma.sync fp16 (f32 acc) ----------------
// C[e*SLOTS+m, n] = sum_k X[rowmap[e*SLOTS+m], k] * Wh[e][n][k]
// BM=128, BN=256, BK=32. 8 warps in 2(M) x 4(N) grid, warp tile 64x64.
// A smem [128 m][40 k] half (pitch 40: conflict-free), B smem [256 n][40 k] half.
#define APH 40
#define BPH 40
#define ABUFH (128*APH)                 // halves per A buffer
#define BBUFH (256*BPH)                 // halves per B buffer
#define MOE_SMEM_BYTES ((2*ABUFH + 2*BBUFH) * 2)   // 61440

template<int KDIM, int NDIM>
__global__ __launch_bounds__(256)
void moe_hmma(const __half* __restrict__ X, const int* __restrict__ rowmap,
              const __half* __restrict__ W, float* __restrict__ C)
{
    constexpr int NC = KDIM / 32;
    extern __shared__ __half smh[];
    __half* Abuf = smh;                 // [2][ABUFH]
    __half* Bbuf = smh + 2*ABUFH;       // [2][BBUFH]

    const int tid = threadIdx.x;
    const int wid = tid >> 5, lane = tid & 31;
    const int wm = wid & 1, wn = wid >> 1;        // 2 x 4 warp grid
    const int m0w = wm*64, n0w = wn*64;
    const int r = lane >> 2, cq = lane & 3;

    const int e  = blockIdx.z;
    const int mt = blockIdx.y;
    const int n0 = blockIdx.x * 256;

    // ---- load setup ----
    const int rowA = tid >> 1, segA = tid & 1;    // 128 rows, 2 threads/row, 32B each
    int token = rowmap[e*SLOTS + mt*128 + rowA];
    if (token < 0) token = 0;
    const __half* srcA = X + (size_t)token * KDIM + segA*16;
    const uint32_t smA = smem_cast(Abuf) + (uint32_t)(rowA*APH + segA*16)*2;

    const int rowB = tid;                          // 256 n-rows, 1 thread/row, 64B each
    const __half* srcB = W + ((size_t)e*NDIM + n0 + rowB) * KDIM;
    const uint32_t smB = smem_cast(Bbuf) + (uint32_t)(rowB*BPH)*2;

    float acc[4][8][4];
    #pragma unroll
    for (int mi = 0; mi < 4; mi++)
        #pragma unroll
        for (int ni = 0; ni < 8; ni++)
            #pragma unroll
            for (int q = 0; q < 4; q++) acc[mi][ni][q] = 0.f;

    auto load_chunk = [&](int c) {
        uint32_t da = smA + (uint32_t)(c & 1)*(ABUFH*2);
        const __half* sa = srcA + c*32;
        CP_ASYNC16(da,      sa);
        CP_ASYNC16(da + 32, sa + 16);   // segA*16 halves apart handled in smA; two 16B per thread-row half
        uint32_t db = smB + (uint32_t)(c & 1)*(BBUFH*2);
        const __half* sb2 = srcB + c*32;
        #pragma unroll
        for (int i = 0; i < 4; i++) CP_ASYNC16(db + i*16, sb2 + i*8);
        CP_COMMIT();
    };
    // NOTE on A loads: each thread covers 32B of its row-half:
    //   segA=0 -> k[0..15], segA=1 -> k[16..31]; the two CP_ASYNC16 above would
    //   overlap, so rewrite: one 16B per (row, seg) with 2 segs of 16 halves each.
    // (handled correctly below by redefining load_chunk)
    auto load_chunk2 = [&](int c) {
        uint32_t da = smA + (uint32_t)(c & 1)*(ABUFH*2);
        const __half* sa = srcA + c*32;
        CP_ASYNC16(da,      sa);        // 8 halves
        CP_ASYNC16(da + 16, sa + 8);    // next 8 halves
        uint32_t db = smB + (uint32_t)(c & 1)*(BBUFH*2);
        const __half* sb2 = srcB + c*32;
        #pragma unroll
        for (int i = 0; i < 4; i++) CP_ASYNC16(db + i*16, sb2 + i*8);
        CP_COMMIT();
    };
    (void)load_chunk;

    load_chunk2(0);
    for (int c = 0; c < NC; c++) {
        if (c + 1 < NC) { load_chunk2(c + 1); CP_WAIT(1); }
        else           { CP_WAIT(0); }
        __syncthreads();

        const __half* As_ = Abuf + (c & 1)*ABUFH;
        const __half* Bs_ = Bbuf + (c & 1)*BBUFH;
        #pragma unroll
        for (int ks = 0; ks < 2; ks++) {           // two k16 steps per BK=32
            const int k0 = ks*16 + cq*2;
            uint32_t a[4][4];
            #pragma unroll
            for (int mi = 0; mi < 4; mi++) {
                int m = m0w + mi*16 + r;
                a[mi][0] = *(const uint32_t*)&As_[m*APH + k0];
                a[mi][1] = *(const uint32_t*)&As_[(m+8)*APH + k0];
                a[mi][2] = *(const uint32_t*)&As_[m*APH + k0 + 8];
                a[mi][3] = *(const uint32_t*)&As_[(m+8)*APH + k0 + 8];
            }
            uint32_t b[8][2];
            #pragma unroll
            for (int ni = 0; ni < 8; ni++) {
                int n = n0w + ni*8 + r;
                b[ni][0] = *(const uint32_t*)&Bs_[n*BPH + k0];
                b[ni][1] = *(const uint32_t*)&Bs_[n*BPH + k0 + 8];
            }
            #pragma unroll
            for (int mi = 0; mi < 4; mi++)
                #pragma unroll
                for (int ni = 0; ni < 8; ni++)
                    mma_f16(acc[mi][ni], a[mi], b[ni]);
        }
        __syncthreads();
    }

    // ---- epilogue ----
    #pragma unroll
    for (int mi = 0; mi < 4; mi++) {
        int mrow = mt*128 + m0w + mi*16 + r;
        float* C0 = C + ((size_t)e*SLOTS + mrow    )*NDIM + n0 + n0w;
        float* C1 = C + ((size_t)e*SLOTS + mrow + 8)*NDIM + n0 + n0w;
        #pragma unroll
        for (int ni = 0; ni < 8; ni++) {
            int col = ni*8 + 2*cq;
            *(float2*)(C0 + col) = make_float2(acc[mi][ni][0], acc[mi][ni][1]);
            *(float2*)(C1 + col) = make_float2(acc[mi][ni][2], acc[mi][ni][3]);
        }
    }
}

// ---------------- attention (fp32, float4 smem reads) ----------------
__global__ __launch_bounds__(64)
void attn_kernel(const float* __restrict__ Q, const float* __restrict__ K,
                 const float* __restrict__ V, float* __restrict__ O)
{
    __shared__ float Ks[32][64];
    __shared__ float Vs[32][64];
    const int bh = blockIdx.y;
    const int b = bh / NH, h = bh % NH;
    const int qi = blockIdx.x*64 + threadIdx.x;
    const size_t qoff = ((size_t)(b*SEQ + qi))*DM + h*64;

    float qr[64];
    #pragma unroll
    for (int d = 0; d < 64; d += 4) {
        float4 t = *(const float4*)&Q[qoff + d];
        qr[d] = t.x*0.125f; qr[d+1] = t.y*0.125f; qr[d+2] = t.z*0.125f; qr[d+3] = t.w*0.125f;
    }
    float m = -1e30f, l = 0.f;
    float o[64];
    #pragma unroll
    for (int d = 0; d < 64; d++) o[d] = 0.f;

    const size_t kbase = ((size_t)b*SEQ)*DM + h*64;
    for (int kt = 0; kt < SEQ; kt += 32) {
        #pragma unroll
        for (int it = 0; it < 8; it++) {
            int f = threadIdx.x + it*64;
            int j = f >> 4; int d4 = (f & 15)*4;
            size_t src = kbase + (size_t)(kt + j)*DM + d4;
            *(float4*)&Ks[j][d4] = *(const float4*)&K[src];
            *(float4*)&Vs[j][d4] = *(const float4*)&V[src];
        }
        __syncthreads();
        float s[32];
        #pragma unroll
        for (int j = 0; j < 32; j++) {
            float a0 = 0.f, a1 = 0.f, a2 = 0.f, a3 = 0.f;
            #pragma unroll
            for (int d4 = 0; d4 < 16; d4++) {
                float4 kv = *(const float4*)&Ks[j][d4*4];
                a0 = fmaf(qr[d4*4+0], kv.x, a0);
                a1 = fmaf(qr[d4*4+1], kv.y, a1);
                a2 = fmaf(qr[d4*4+2], kv.z, a2);
                a3 = fmaf(qr[d4*4+3], kv.w, a3);
            }
            s[j] = (a0 + a1) + (a2 + a3);
        }
        float tmax = m;
        #pragma unroll
        for (int j = 0; j < 32; j++) tmax = fmaxf(tmax, s[j]);
        float f = expf(m - tmax);
        l *= f;
        #pragma unroll
        for (int d = 0; d < 64; d++) o[d] *= f;
        #pragma unroll
        for (int j = 0; j < 32; j++) {
            float p = expf(s[j] - tmax);
            l += p;
            #pragma unroll
            for (int d4 = 0; d4 < 16; d4++) {
                float4 vv = *(const float4*)&Vs[j][d4*4];
                o[d4*4+0] = fmaf(p, vv.x, o[d4*4+0]);
                o[d4*4+1] = fmaf(p, vv.y, o[d4*4+1]);
                o[d4*4+2] = fmaf(p, vv.z, o[d4*4+2]);
                o[d4*4+3] = fmaf(p, vv.w, o[d4*4+3]);
            }
        }
        m = tmax;
        __syncthreads();
    }
    float inv = 1.f / l;
    #pragma unroll
    for (int d = 0; d < 64; d += 4) {
        *(float4*)&O[qoff + d] = make_float4(o[d]*inv, o[d+1]*inv, o[d+2]*inv, o[d+3]*inv);
    }
}

// ---------------- layernorm (optional fp16 second output) ----------------
__global__ void ln_kernel(const float* __restrict__ X, float* __restrict__ Y,
                          __half* __restrict__ Yh,
                          const float* __restrict__ gg, const float* __restrict__ bb, int len)
{
    __shared__ float sb[32];
    const int row = blockIdx.x;
    const float* xr = X + (size_t)row*len;
    float sum = 0.f;
    for (int c = threadIdx.x; c < len; c += blockDim.x) sum += xr[c];
    float mean = blk_sum(sum, sb) / len;
    float s2 = 0.f;
    for (int c = threadIdx.x; c < len; c += blockDim.x) { float d = xr[c]-mean; s2 += d*d; }
    float var = blk_sum(s2, sb) / len;
    float r = rsqrtf(var + EPSV);
    for (int c = threadIdx.x; c < len; c += blockDim.x) {
        float v = (xr[c]-mean)*r*gg[c] + bb[c];
        Y[(size_t)row*len + c] = v;
        if (Yh) Yh[(size_t)row*len + c] = __float2half_rn(v);
    }
}

// ---------------- gating (fp32 exact) ----------------
__global__ void gate_kernel(const float* __restrict__ Xres, const float* __restrict__ wg)
{
    __shared__ float xr[DM];
    __shared__ float lg[NE];
    const int tt = blockIdx.x;
    const int grp = tt >> 11, ti = tt & 2047;
    const int row = ((ti >> 8) * SEQ) + grp*256 + (ti & 255);
    for (int c = threadIdx.x; c < DM; c += blockDim.x) xr[c] = Xres[(size_t)row*DM + c];
    __syncthreads();
    if (threadIdx.x < NE) {
        float acc = 0.f;
        #pragma unroll 8
        for (int d = 0; d < DM; d++) acc = fmaf(xr[d], wg[d*NE + threadIdx.x], acc);
        lg[threadIdx.x] = acc;
    }
    __syncthreads();
    if (threadIdx.x == 0) {
        int i1 = 0; float v1 = lg[0];
        for (int e2 = 1; e2 < NE; e2++) if (lg[e2] > v1) { v1 = lg[e2]; i1 = e2; }
        int i2 = -1; float v2 = -1e30f;
        for (int e2 = 0; e2 < NE; e2++) if (e2 != i1 && lg[e2] > v2) { v2 = lg[e2]; i2 = e2; }
        float r2 = expf(v2 - v1);
        float inv = 1.f / (1.f + r2);
        g_e1[tt] = i1; g_e2[tt] = i2;
        g_wa[tt] = inv; g_wb[tt] = r2 * inv;
    }
}

// ---------------- GShard slot assignment (one block per group) ----------------
__global__ void assign_kernel()
{
    __shared__ int scnt[NE];
    const int grp = blockIdx.x;
    const int tid = threadIdx.x, lane = tid & 31, e = tid >> 5;
    for (int i = tid; i < NE*GOFF; i += blockDim.x) {
        int ee = i / GOFF, s = i % GOFF;
        g_rowg[ee*SLOTS + grp*GOFF + s] = -1;
        g_rowl[ee*SLOTS + grp*GOFF + s] = -1;
    }
    __syncthreads();
    int cnt = 0;
    for (int base = 0; base < TG; base += 32) {
        int ti = base + lane;
        int tt = grp*TG + ti;
        bool mm = (g_e1[tt] == e);
        unsigned bal = __ballot_sync(0xffffffffu, mm);
        if (mm) {
            int loc = cnt + __popc(bal & ((1u << lane) - 1u));
            if (loc < CAP) {
                int srow = grp*GOFF + loc;
                g_s1[tt] = srow;
                int row = ((ti >> 8) * SEQ) + grp*256 + (ti & 255);
                g_rowg[e*SLOTS + srow] = row;
                g_rowl[e*SLOTS + srow] = tt;
            } else g_s1[tt] = -1;
        }
        cnt += __popc(bal);
    }
    if (lane == 0) scnt[e] = cnt;
    __syncthreads();
    cnt = scnt[e];
    for (int base = 0; base < TG; base += 32) {
        int ti = base + lane;
        int tt = grp*TG + ti;
        bool mm = (g_e2[tt] == e);
        unsigned bal = __ballot_sync(0xffffffffu, mm);
        if (mm) {
            int loc = cnt + __popc(bal & ((1u << lane) - 1u));
            if (loc < CAP) {
                int srow = grp*GOFF + loc;
                g_s2[tt] = srow;
                int row = ((ti >> 8) * SEQ) + grp*256 + (ti & 255);
                g_rowg[e*SLOTS + srow] = row;
                g_rowl[e*SLOTS + srow] = tt;
            } else g_s2[tt] = -1;
        }
        cnt += __popc(bal);
    }
}

// ---------------- combine MoE1 + bias + LN + relu -> fp16 ----------------
__global__ void combine1_kernel(const float* __restrict__ b1)
{
    __shared__ float sb[32];
    const int tt = blockIdx.x;
    const int grp = tt >> 11;
    const float* lng = g_lnp[2*grp];
    const float* lnb = g_lnp[2*grp+1];
    const int e1 = g_e1[tt], e2 = g_e2[tt], s1 = g_s1[tt], s2 = g_s2[tt];
    const float wa = g_wa[tt], wb = g_wb[tt];
    const float* p1 = (s1 >= 0) ? &g_sloth[((size_t)e1*SLOTS + s1)*DI] : (const float*)0;
    const float* p2 = (s2 >= 0) ? &g_sloth[((size_t)e2*SLOTS + s2)*DI] : (const float*)0;
    float vals[8];
    float sum = 0.f;
    #pragma unroll
    for (int i = 0; i < 8; i++) {
        int c = threadIdx.x + i*256;
        float hv = 0.f;
        if (p1) hv += wa * (p1[c] + b1[e1*DI + c]);
        if (p2) hv += wb * (p2[c] + b1[e2*DI + c]);
        vals[i] = hv; sum += hv;
    }
    float mean = blk_sum(sum, sb) / DI;
    float s2s = 0.f;
    #pragma unroll
    for (int i = 0; i < 8; i++) { float d = vals[i]-mean; s2s += d*d; }
    float var = blk_sum(s2s, sb) / DI;
    float r = rsqrtf(var + EPSV);
    #pragma unroll
    for (int i = 0; i < 8; i++) {
        int c = threadIdx.x + i*256;
        float v = fmaxf((vals[i]-mean)*r*lng[c] + lnb[c], 0.f);
        g_hpost[(size_t)tt*DI + c] = __float2half_rn(v);
    }
}

// ---------------- combine MoE2 + bias + residual ----------------
__global__ void combine2_kernel(const float* __restrict__ b2)
{
    const int tt = blockIdx.x;
    const int grp = tt >> 11, ti = tt & 2047;
    const int e1 = g_e1[tt], e2 = g_e2[tt], s1 = g_s1[tt], s2 = g_s2[tt];
    const float wa = g_wa[tt], wb = g_wb[tt];
    const int row = ((ti >> 8) * SEQ) + grp*256 + (ti & 255);
    #pragma unroll
    for (int i = 0; i < 4; i++) {
        int c = threadIdx.x + i*128;
        float y = 0.f;
        if (s1 >= 0) y += wa * (g_sloty[((size_t)e1*SLOTS + s1)*DM + c] + b2[e1*DM + c]);
        if (s2 >= 0) y += wb * (g_sloty[((size_t)e2*SLOTS + s2)*DM + c] + b2[e2*DM + c]);
        g_y[(size_t)row*DM + c] = y + g_res[(size_t)row*DM + c];
    }
}

__global__ void set_lnp_kernel(const float* a0, const float* a1, const float* a2, const float* a3,
                               const float* a4, const float* a5, const float* a6, const float* a7)
{
    g_lnp[0]=a0; g_lnp[1]=a1; g_lnp[2]=a2; g_lnp[3]=a3;
    g_lnp[4]=a4; g_lnp[5]=a5; g_lnp[6]=a6; g_lnp[7]=a7;
}

// ---------------- launch ----------------
extern "C" void kernel_launch(void* const* d_in, const int* in_sizes, int n_in,
                              void* d_out, int out_size)
{
    const float *x=0,*wq=0,*wk=0,*wv=0,*wo=0,*ln_attn_g=0,*ln_attn_b=0,*wg1=0,*w1=0,*b1=0,
                *w2=0,*b2=0,*ln_out_g=0,*ln_out_b=0;
    const float* ln2048[8] = {0,0,0,0,0,0,0,0};
    int c262=0,c512=0,c12k=0,c25m=0,c49k=0,c2k=0;
    for (int i = 0; i < n_in; i++) {
        const float* p = (const float*)d_in[i];
        switch (in_sizes[i]) {
            case 4194304: x = p; break;
            case 262144:
                if (c262==0) wq=p; else if (c262==1) wk=p; else if (c262==2) wv=p; else wo=p;
                c262++; break;
            case 512:
                if (c512==0) ln_attn_g=p; else if (c512==1) ln_attn_b=p;
                else if (c512==2) ln_out_g=p; else ln_out_b=p;
                c512++; break;
            case 12288:
                if (c12k==0) wg1=p; else b2=p;
                c12k++; break;
            case 25165824:
                if (c25m==0) w1=p; else w2=p;
                c25m++; break;
            case 49152:
                if (c49k==0) b1=p;
                c49k++; break;
            case 2048:
                if (c2k < 8) ln2048[c2k] = p;
                c2k++; break;
            default: break;
        }
    }

    float *p_q,*p_k,*p_v,*p_ctx,*p_tmp,*p_res,*p_y,*p_sloth,*p_sloty;
    __half *p_resh,*p_wh1,*p_wh2,*p_hpost;
    int *p_rowg,*p_rowl;
    cudaGetSymbolAddress((void**)&p_q,     g_q);
    cudaGetSymbolAddress((void**)&p_k,     g_k);
    cudaGetSymbolAddress((void**)&p_v,     g_v);
    cudaGetSymbolAddress((void**)&p_ctx,   g_ctx);
    cudaGetSymbolAddress((void**)&p_tmp,   g_tmp);
    cudaGetSymbolAddress((void**)&p_res,   g_res);
    cudaGetSymbolAddress((void**)&p_resh,  g_resh);
    cudaGetSymbolAddress((void**)&p_y,     g_y);
    cudaGetSymbolAddress((void**)&p_wh1,   g_wh1);
    cudaGetSymbolAddress((void**)&p_wh2,   g_wh2);
    cudaGetSymbolAddress((void**)&p_sloth, g_sloth);
    cudaGetSymbolAddress((void**)&p_sloty, g_sloty);
    cudaGetSymbolAddress((void**)&p_hpost, g_hpost);
    cudaGetSymbolAddress((void**)&p_rowg,  g_rowg);
    cudaGetSymbolAddress((void**)&p_rowl,  g_rowl);

    float* out = (float*)d_out;

    cudaFuncSetAttribute(moe_hmma<DM, DI>, cudaFuncAttributeMaxDynamicSharedMemorySize, MOE_SMEM_BYTES);
    cudaFuncSetAttribute(moe_hmma<DI, DM>, cudaFuncAttributeMaxDynamicSharedMemorySize, MOE_SMEM_BYTES);

    // 0) weight prep: transpose + fp16 convert; LN param table
    transpose_half<<<dim3(DI/32, DM/32, NE), dim3(32,8)>>>(w1, p_wh1, DM, DI);
    transpose_half<<<dim3(DM/32, DI/32, NE), dim3(32,8)>>>(w2, p_wh2, DI, DM);
    set_lnp_kernel<<<1,1>>>(ln2048[0],ln2048[1],ln2048[2],ln2048[3],
                            ln2048[4],ln2048[5],ln2048[6],ln2048[7]);

    // 1) QKV projections (fp32)
    dim3 gqkv(DM/128, NROWS/128);
    sgemm128<<<gqkv, 256>>>(x, wq, p_q, NROWS, DM, DM, (const float*)0, 0);
    sgemm128<<<gqkv, 256>>>(x, wk, p_k, NROWS, DM, DM, (const float*)0, 0);
    sgemm128<<<gqkv, 256>>>(x, wv, p_v, NROWS, DM, DM, (const float*)0, 0);

    // 2) attention (fp32)
    attn_kernel<<<dim3(SEQ/64, NB*NH), 64>>>(p_q, p_k, p_v, p_ctx);

    // 3) output projection + relu + residual, then LN (exact + fp16 copy)
    sgemm128<<<gqkv, 256>>>(p_ctx, wo, p_tmp, NROWS, DM, DM, x, 1);
    ln_kernel<<<NROWS, 256>>>(p_tmp, p_res, p_resh, ln_attn_g, ln_attn_b, DM);

    // 4) routing (all 4 groups)
    gate_kernel<<<NTOK, 128>>>(p_res, wg1);
    assign_kernel<<<NGRP, NE*32>>>();

    // 5) MoE GEMM1 (HMMA fp16), combine, GEMM2, combine
    moe_hmma<DM, DI><<<dim3(DI/256, SLOTS/128, NE), 256, MOE_SMEM_BYTES>>>(p_resh, p_rowg, p_wh1, p_sloth);
    combine1_kernel<<<NTOK, 256>>>(b1);
    moe_hmma<DI, DM><<<dim3(DM/256, SLOTS/128, NE), 256, MOE_SMEM_BYTES>>>(p_hpost, p_rowl, p_wh2, p_sloty);
    combine2_kernel<<<NTOK, 128>>>(b2);

    // 6) final LN
    ln_kernel<<<NROWS, 256>>>(p_y, out, (__half*)0, ln_out_g, ln_out_b, DM);

    (void)out_size;
}

// round 6
// speedup vs baseline: 2.6611x; 1.0739x over previous
#include <cuda_runtime.h>
#include <cuda_fp16.h>
#include <cstdint>
#include <cstddef>

// ---------------- problem constants ----------------
#define NB    8
#define SEQ   1024
#define DM    512
#define NH    8
#define DI    2048
#define NE    24
#define CAP   171
#define TG    2048
#define NGRP  4
#define NROWS (NB*SEQ)      // 8192
#define NTOK  (NGRP*TG)     // 8192
#define SLOTS 768
#define GOFF  192
#define EPSV  1e-6f

// ---------------- device scratch ----------------
__device__ float  g_q[NROWS*DM];
__device__ float  g_k[NROWS*DM];
__device__ float  g_v[NROWS*DM];
__device__ float  g_ctx[NROWS*DM];
__device__ float  g_tmp[NROWS*DM];
__device__ float  g_res[NROWS*DM];     // post-attention LN (exact: gating + residual)
__device__ __half g_resh[NROWS*DM];    // fp16 copy (MoE GEMM1 input)
__device__ __half g_wh1[(size_t)NE*DI*DM];   // w1 half, transposed [e][n=DI][k=DM]
__device__ __half g_wh2[(size_t)NE*DM*DI];   // w2 half, transposed [e][n=DM][k=DI]
__device__ float  g_sloth[(size_t)NE*SLOTS*DI];
__device__ float  g_sloty[(size_t)NE*SLOTS*DM];
__device__ __half g_hpost[(size_t)NTOK*DI];  // fp16 (MoE GEMM2 input)
__device__ int    g_e1[NTOK], g_e2[NTOK], g_s1[NTOK], g_s2[NTOK];
__device__ float  g_wa[NTOK], g_wb[NTOK];
__device__ int    g_rowg[NE*SLOTS];
__device__ int    g_rowl[NE*SLOTS];
__device__ const float* g_lnp[8];

// ---------------- PTX helpers ----------------
__device__ __forceinline__ uint32_t smem_cast(const void* p) {
    uint32_t a;
    asm("{ .reg .u64 t; cvta.to.shared.u64 t, %1; cvt.u32.u64 %0, t; }" : "=r"(a) : "l"(p));
    return a;
}
#define CP_ASYNC16(dst, src) \
    asm volatile("cp.async.cg.shared.global [%0], [%1], 16;" :: "r"(dst), "l"(src) : "memory")
#define CP_COMMIT() asm volatile("cp.async.commit_group;" ::: "memory")
#define CP_WAIT(n)  asm volatile("cp.async.wait_group %0;" :: "n"(n) : "memory")

__device__ __forceinline__ void mma_f16(float* d, const uint32_t* a, const uint32_t* b) {
    asm volatile(
        "mma.sync.aligned.m16n8k16.row.col.f32.f16.f16.f32 "
        "{%0,%1,%2,%3}, {%4,%5,%6,%7}, {%8,%9}, {%0,%1,%2,%3};"
        : "+f"(d[0]), "+f"(d[1]), "+f"(d[2]), "+f"(d[3])
        : "r"(a[0]), "r"(a[1]), "r"(a[2]), "r"(a[3]), "r"(b[0]), "r"(b[1]));
}

// ---------------- block reduction ----------------
__device__ __forceinline__ float blk_sum(float v, float* sb) {
    int lane = threadIdx.x & 31, wid = threadIdx.x >> 5;
    #pragma unroll
    for (int o = 16; o; o >>= 1) v += __shfl_down_sync(0xffffffffu, v, o);
    if (lane == 0) sb[wid] = v;
    __syncthreads();
    int nw = (blockDim.x + 31) >> 5;
    if (wid == 0) {
        float r = (lane < nw) ? sb[lane] : 0.f;
        #pragma unroll
        for (int o = 16; o; o >>= 1) r += __shfl_down_sync(0xffffffffu, r, o);
        if (lane == 0) sb[0] = r;
    }
    __syncthreads();
    float r = sb[0];
    __syncthreads();
    return r;
}

// ---------------- weight prep: W[e][k][n] float -> Wh[e][n][k] half ----------------
__global__ void transpose_half(const float* __restrict__ W, __half* __restrict__ Wh,
                               int K, int N)
{
    __shared__ float t[32][33];
    const int e = blockIdx.z;
    const int n0 = blockIdx.x * 32, k0 = blockIdx.y * 32;
    const float* We = W + (size_t)e * K * N;
    __half* Whe = Wh + (size_t)e * K * N;
    const int tx = threadIdx.x, ty = threadIdx.y;   // 32 x 8
    #pragma unroll
    for (int i = 0; i < 32; i += 8)
        t[ty + i][tx] = We[(size_t)(k0 + ty + i) * N + n0 + tx];
    __syncthreads();
    #pragma unroll
    for (int i = 0; i < 32; i += 8)
        Whe[(size_t)(n0 + ty + i) * K + k0 + tx] = __float2half_rn(t[tx][ty + i]);
}

// ---------------- dense fp32 SGEMM body (128x128x16, register-prefetch pipeline) ----------------
__device__ __forceinline__ void sgemm_body(const float* __restrict__ A, const float* __restrict__ B,
                                           float* __restrict__ C, int N, int K,
                                           const float* __restrict__ R, int epi,
                                           int bx, int by)
{
    __shared__ float As[16][128];
    __shared__ float Bs[16][128];
    const int tid = threadIdx.x;
    const int trow = tid >> 4, tcol = tid & 15;

    float acc[8][8];
    #pragma unroll
    for (int i = 0; i < 8; i++)
        #pragma unroll
        for (int j = 0; j < 8; j++) acc[i][j] = 0.f;

    const int aRow = tid >> 1, aCol = (tid & 1) * 8;
    const int bRow = tid >> 5, bCol = (tid & 31) * 4;
    const float* Ap = A + (size_t)(by*128 + aRow)*K + aCol;
    const float* Bp = B + (size_t)bRow*N + bx*128 + bCol;

    float4 a0 = *(const float4*)(Ap);
    float4 a1 = *(const float4*)(Ap + 4);
    float4 b0 = *(const float4*)(Bp);
    float4 b1 = *(const float4*)(Bp + (size_t)8*N);

    for (int k0 = 0; k0 < K; k0 += 16) {
        As[aCol+0][aRow]=a0.x; As[aCol+1][aRow]=a0.y; As[aCol+2][aRow]=a0.z; As[aCol+3][aRow]=a0.w;
        As[aCol+4][aRow]=a1.x; As[aCol+5][aRow]=a1.y; As[aCol+6][aRow]=a1.z; As[aCol+7][aRow]=a1.w;
        *(float4*)&Bs[bRow  ][bCol] = b0;
        *(float4*)&Bs[bRow+8][bCol] = b1;
        __syncthreads();
        if (k0 + 16 < K) {                      // prefetch next chunk (overlaps compute)
            a0 = *(const float4*)(Ap + k0 + 16);
            a1 = *(const float4*)(Ap + k0 + 20);
            b0 = *(const float4*)(Bp + (size_t)(k0+16)*N);
            b1 = *(const float4*)(Bp + (size_t)(k0+24)*N);
        }
        #pragma unroll
        for (int kk = 0; kk < 16; kk++) {
            float4 ar0 = *(const float4*)&As[kk][trow*8];
            float4 ar1 = *(const float4*)&As[kk][trow*8+4];
            float4 br0 = *(const float4*)&Bs[kk][tcol*4];
            float4 br1 = *(const float4*)&Bs[kk][tcol*4+64];
            float a_[8] = {ar0.x,ar0.y,ar0.z,ar0.w,ar1.x,ar1.y,ar1.z,ar1.w};
            float b_[8] = {br0.x,br0.y,br0.z,br0.w,br1.x,br1.y,br1.z,br1.w};
            #pragma unroll
            for (int i = 0; i < 8; i++)
                #pragma unroll
                for (int j = 0; j < 8; j++)
                    acc[i][j] = fmaf(a_[i], b_[j], acc[i][j]);
        }
        __syncthreads();
    }
    #pragma unroll
    for (int i = 0; i < 8; i++) {
        int row = by*128 + trow*8 + i;
        #pragma unroll
        for (int g = 0; g < 2; g++) {
            int col = bx*128 + tcol*4 + g*64;
            float4 v = make_float4(acc[i][g*4], acc[i][g*4+1], acc[i][g*4+2], acc[i][g*4+3]);
            if (epi == 1) {
                const float4 r = *(const float4*)&R[(size_t)row*N + col];
                v.x = fmaxf(v.x, 0.f) + r.x;
                v.y = fmaxf(v.y, 0.f) + r.y;
                v.z = fmaxf(v.z, 0.f) + r.z;
                v.w = fmaxf(v.w, 0.f) + r.w;
            }
            *(float4*)&C[(size_t)row*N + col] = v;
        }
    }
}

__global__ __launch_bounds__(256)
void sgemm128(const float* __restrict__ A, const float* __restrict__ B,
              float* __restrict__ C, int N, int K,
              const float* __restrict__ R, int epi)
{
    sgemm_body(A, B, C, N, K, R, epi, blockIdx.x, blockIdx.y);
}

// fused QKV: grid.z selects which projection
__global__ __launch_bounds__(256)
void sgemm_qkv(const float* __restrict__ A,
               const float* __restrict__ Bq, const float* __restrict__ Bk, const float* __restrict__ Bv,
               float* __restrict__ Cq, float* __restrict__ Ck, float* __restrict__ Cv)
{
    const float* B = (blockIdx.z == 0) ? Bq : (blockIdx.z == 1) ? Bk : Bv;
    float*       C = (blockIdx.z == 0) ? Cq : (blockIdx.z == 1) ? Ck : Cv;
    sgemm_body(A, B, C, DM, DM, (const float*)0, 0, blockIdx.x, blockIdx.y);
}

// ---------------- MoE grouped GEMM via mma.sync fp16 (f32 acc) ----------------
#define APH 40
#define BPH 40
#define ABUFH (128*APH)
#define BBUFH (256*BPH)
#define MOE_SMEM_BYTES ((2*ABUFH + 2*BBUFH) * 2)   // 61440

template<int KDIM, int NDIM>
__global__ __launch_bounds__(256)
void moe_hmma(const __half* __restrict__ X, const int* __restrict__ rowmap,
              const __half* __restrict__ W, float* __restrict__ C)
{
    constexpr int NC = KDIM / 32;
    extern __shared__ __half smh[];
    __half* Abuf = smh;
    __half* Bbuf = smh + 2*ABUFH;

    const int tid = threadIdx.x;
    const int wid = tid >> 5, lane = tid & 31;
    const int wm = wid & 1, wn = wid >> 1;
    const int m0w = wm*64, n0w = wn*64;
    const int r = lane >> 2, cq = lane & 3;

    const int e  = blockIdx.z;
    const int mt = blockIdx.y;
    const int n0 = blockIdx.x * 256;

    const int rowA = tid >> 1, segA = tid & 1;
    int token = rowmap[e*SLOTS + mt*128 + rowA];
    if (token < 0) token = 0;
    const __half* srcA = X + (size_t)token * KDIM + segA*16;
    const uint32_t smA = smem_cast(Abuf) + (uint32_t)(rowA*APH + segA*16)*2;

    const int rowB = tid;
    const __half* srcB = W + ((size_t)e*NDIM + n0 + rowB) * KDIM;
    const uint32_t smB = smem_cast(Bbuf) + (uint32_t)(rowB*BPH)*2;

    float acc[4][8][4];
    #pragma unroll
    for (int mi = 0; mi < 4; mi++)
        #pragma unroll
        for (int ni = 0; ni < 8; ni++)
            #pragma unroll
            for (int q = 0; q < 4; q++) acc[mi][ni][q] = 0.f;

    auto load_chunk = [&](int c) {
        uint32_t da = smA + (uint32_t)(c & 1)*(ABUFH*2);
        const __half* sa = srcA + c*32;
        CP_ASYNC16(da,      sa);
        CP_ASYNC16(da + 16, sa + 8);
        uint32_t db = smB + (uint32_t)(c & 1)*(BBUFH*2);
        const __half* sb2 = srcB + c*32;
        #pragma unroll
        for (int i = 0; i < 4; i++) CP_ASYNC16(db + i*16, sb2 + i*8);
        CP_COMMIT();
    };

    load_chunk(0);
    for (int c = 0; c < NC; c++) {
        if (c + 1 < NC) { load_chunk(c + 1); CP_WAIT(1); }
        else           { CP_WAIT(0); }
        __syncthreads();

        const __half* As_ = Abuf + (c & 1)*ABUFH;
        const __half* Bs_ = Bbuf + (c & 1)*BBUFH;
        #pragma unroll
        for (int ks = 0; ks < 2; ks++) {
            const int k0 = ks*16 + cq*2;
            uint32_t a[4][4];
            #pragma unroll
            for (int mi = 0; mi < 4; mi++) {
                int m = m0w + mi*16 + r;
                a[mi][0] = *(const uint32_t*)&As_[m*APH + k0];
                a[mi][1] = *(const uint32_t*)&As_[(m+8)*APH + k0];
                a[mi][2] = *(const uint32_t*)&As_[m*APH + k0 + 8];
                a[mi][3] = *(const uint32_t*)&As_[(m+8)*APH + k0 + 8];
            }
            uint32_t b[8][2];
            #pragma unroll
            for (int ni = 0; ni < 8; ni++) {
                int n = n0w + ni*8 + r;
                b[ni][0] = *(const uint32_t*)&Bs_[n*BPH + k0];
                b[ni][1] = *(const uint32_t*)&Bs_[n*BPH + k0 + 8];
            }
            #pragma unroll
            for (int mi = 0; mi < 4; mi++)
                #pragma unroll
                for (int ni = 0; ni < 8; ni++)
                    mma_f16(acc[mi][ni], a[mi], b[ni]);
        }
        __syncthreads();
    }

    #pragma unroll
    for (int mi = 0; mi < 4; mi++) {
        int mrow = mt*128 + m0w + mi*16 + r;
        float* C0 = C + ((size_t)e*SLOTS + mrow    )*NDIM + n0 + n0w;
        float* C1 = C + ((size_t)e*SLOTS + mrow + 8)*NDIM + n0 + n0w;
        #pragma unroll
        for (int ni = 0; ni < 8; ni++) {
            int col = ni*8 + 2*cq;
            *(float2*)(C0 + col) = make_float2(acc[mi][ni][0], acc[mi][ni][1]);
            *(float2*)(C1 + col) = make_float2(acc[mi][ni][2], acc[mi][ni][3]);
        }
    }
}

// ---------------- attention (fp32, cp.async double-buffered tiles, __expf) ----------------
__global__ __launch_bounds__(64)
void attn_kernel(const float* __restrict__ Q, const float* __restrict__ K,
                 const float* __restrict__ V, float* __restrict__ O)
{
    __shared__ float Ks[2][32][64];
    __shared__ float Vs[2][32][64];
    const int bh = blockIdx.y;
    const int b = bh / NH, h = bh % NH;
    const int qi = blockIdx.x*64 + threadIdx.x;
    const size_t qoff = ((size_t)(b*SEQ + qi))*DM + h*64;
    const size_t kbase = ((size_t)b*SEQ)*DM + h*64;

    const uint32_t sK = smem_cast(Ks);
    const uint32_t sV = smem_cast(Vs);

    float qr[64];
    #pragma unroll
    for (int d = 0; d < 64; d += 4) {
        float4 t = *(const float4*)&Q[qoff + d];
        qr[d] = t.x*0.125f; qr[d+1] = t.y*0.125f; qr[d+2] = t.z*0.125f; qr[d+3] = t.w*0.125f;
    }
    float m = -1e30f, l = 0.f;
    float o[64];
    #pragma unroll
    for (int d = 0; d < 64; d++) o[d] = 0.f;

    auto load_tile = [&](int kt, int buf) {
        #pragma unroll
        for (int it = 0; it < 8; it++) {
            int f = threadIdx.x + it*64;
            int j = f >> 4; int d4 = (f & 15)*4;
            uint32_t off = (uint32_t)(buf*8192 + (j*64 + d4)*4);
            size_t src = kbase + (size_t)(kt + j)*DM + d4;
            CP_ASYNC16(sK + off, &K[src]);
            CP_ASYNC16(sV + off, &V[src]);
        }
        CP_COMMIT();
    };

    load_tile(0, 0);
    for (int t = 0; t < SEQ/32; t++) {
        const int buf = t & 1;
        if (t + 1 < SEQ/32) { load_tile((t+1)*32, (t+1) & 1); CP_WAIT(1); }
        else                { CP_WAIT(0); }
        __syncthreads();

        float s[32];
        #pragma unroll
        for (int j = 0; j < 32; j++) {
            float a0 = 0.f, a1 = 0.f, a2 = 0.f, a3 = 0.f;
            #pragma unroll
            for (int d4 = 0; d4 < 16; d4++) {
                float4 kv = *(const float4*)&Ks[buf][j][d4*4];
                a0 = fmaf(qr[d4*4+0], kv.x, a0);
                a1 = fmaf(qr[d4*4+1], kv.y, a1);
                a2 = fmaf(qr[d4*4+2], kv.z, a2);
                a3 = fmaf(qr[d4*4+3], kv.w, a3);
            }
            s[j] = (a0 + a1) + (a2 + a3);
        }
        float tmax = m;
        #pragma unroll
        for (int j = 0; j < 32; j++) tmax = fmaxf(tmax, s[j]);
        float f = __expf(m - tmax);
        l *= f;
        #pragma unroll
        for (int d = 0; d < 64; d++) o[d] *= f;
        #pragma unroll
        for (int j = 0; j < 32; j++) {
            float p = __expf(s[j] - tmax);
            l += p;
            #pragma unroll
            for (int d4 = 0; d4 < 16; d4++) {
                float4 vv = *(const float4*)&Vs[buf][j][d4*4];
                o[d4*4+0] = fmaf(p, vv.x, o[d4*4+0]);
                o[d4*4+1] = fmaf(p, vv.y, o[d4*4+1]);
                o[d4*4+2] = fmaf(p, vv.z, o[d4*4+2]);
                o[d4*4+3] = fmaf(p, vv.w, o[d4*4+3]);
            }
        }
        m = tmax;
        __syncthreads();
    }
    float inv = 1.f / l;
    #pragma unroll
    for (int d = 0; d < 64; d += 4) {
        *(float4*)&O[qoff + d] = make_float4(o[d]*inv, o[d+1]*inv, o[d+2]*inv, o[d+3]*inv);
    }
}

// ---------------- layernorm (optional fp16 second output) ----------------
__global__ void ln_kernel(const float* __restrict__ X, float* __restrict__ Y,
                          __half* __restrict__ Yh,
                          const float* __restrict__ gg, const float* __restrict__ bb, int len)
{
    __shared__ float sb[32];
    const int row = blockIdx.x;
    const float* xr = X + (size_t)row*len;
    float sum = 0.f;
    for (int c = threadIdx.x; c < len; c += blockDim.x) sum += xr[c];
    float mean = blk_sum(sum, sb) / len;
    float s2 = 0.f;
    for (int c = threadIdx.x; c < len; c += blockDim.x) { float d = xr[c]-mean; s2 += d*d; }
    float var = blk_sum(s2, sb) / len;
    float r = rsqrtf(var + EPSV);
    for (int c = threadIdx.x; c < len; c += blockDim.x) {
        float v = (xr[c]-mean)*r*gg[c] + bb[c];
        Y[(size_t)row*len + c] = v;
        if (Yh) Yh[(size_t)row*len + c] = __float2half_rn(v);
    }
}

// ---------------- gating (fp32 exact — byte-identical logic to R4/R5) ----------------
__global__ void gate_kernel(const float* __restrict__ Xres, const float* __restrict__ wg)
{
    __shared__ float xr[DM];
    __shared__ float lg[NE];
    const int tt = blockIdx.x;
    const int grp = tt >> 11, ti = tt & 2047;
    const int row = ((ti >> 8) * SEQ) + grp*256 + (ti & 255);
    for (int c = threadIdx.x; c < DM; c += blockDim.x) xr[c] = Xres[(size_t)row*DM + c];
    __syncthreads();
    if (threadIdx.x < NE) {
        float acc = 0.f;
        #pragma unroll 8
        for (int d = 0; d < DM; d++) acc = fmaf(xr[d], wg[d*NE + threadIdx.x], acc);
        lg[threadIdx.x] = acc;
    }
    __syncthreads();
    if (threadIdx.x == 0) {
        int i1 = 0; float v1 = lg[0];
        for (int e2 = 1; e2 < NE; e2++) if (lg[e2] > v1) { v1 = lg[e2]; i1 = e2; }
        int i2 = -1; float v2 = -1e30f;
        for (int e2 = 0; e2 < NE; e2++) if (e2 != i1 && lg[e2] > v2) { v2 = lg[e2]; i2 = e2; }
        float r2 = expf(v2 - v1);
        float inv = 1.f / (1.f + r2);
        g_e1[tt] = i1; g_e2[tt] = i2;
        g_wa[tt] = inv; g_wb[tt] = r2 * inv;
    }
}

// ---------------- GShard slot assignment ----------------
__global__ void assign_kernel()
{
    __shared__ int scnt[NE];
    const int grp = blockIdx.x;
    const int tid = threadIdx.x, lane = tid & 31, e = tid >> 5;
    for (int i = tid; i < NE*GOFF; i += blockDim.x) {
        int ee = i / GOFF, s = i % GOFF;
        g_rowg[ee*SLOTS + grp*GOFF + s] = -1;
        g_rowl[ee*SLOTS + grp*GOFF + s] = -1;
    }
    __syncthreads();
    int cnt = 0;
    for (int base = 0; base < TG; base += 32) {
        int ti = base + lane;
        int tt = grp*TG + ti;
        bool mm = (g_e1[tt] == e);
        unsigned bal = __ballot_sync(0xffffffffu, mm);
        if (mm) {
            int loc = cnt + __popc(bal & ((1u << lane) - 1u));
            if (loc < CAP) {
                int srow = grp*GOFF + loc;
                g_s1[tt] = srow;
                int row = ((ti >> 8) * SEQ) + grp*256 + (ti & 255);
                g_rowg[e*SLOTS + srow] = row;
                g_rowl[e*SLOTS + srow] = tt;
            } else g_s1[tt] = -1;
        }
        cnt += __popc(bal);
    }
    if (lane == 0) scnt[e] = cnt;
    __syncthreads();
    cnt = scnt[e];
    for (int base = 0; base < TG; base += 32) {
        int ti = base + lane;
        int tt = grp*TG + ti;
        bool mm = (g_e2[tt] == e);
        unsigned bal = __ballot_sync(0xffffffffu, mm);
        if (mm) {
            int loc = cnt + __popc(bal & ((1u << lane) - 1u));
            if (loc < CAP) {
                int srow = grp*GOFF + loc;
                g_s2[tt] = srow;
                int row = ((ti >> 8) * SEQ) + grp*256 + (ti & 255);
                g_rowg[e*SLOTS + srow] = row;
                g_rowl[e*SLOTS + srow] = tt;
            } else g_s2[tt] = -1;
        }
        cnt += __popc(bal);
    }
}

// ---------------- combine MoE1 + bias + LN + relu -> fp16 ----------------
__global__ void combine1_kernel(const float* __restrict__ b1)
{
    __shared__ float sb[32];
    const int tt = blockIdx.x;
    const int grp = tt >> 11;
    const float* lng = g_lnp[2*grp];
    const float* lnb = g_lnp[2*grp+1];
    const int e1 = g_e1[tt], e2 = g_e2[tt], s1 = g_s1[tt], s2 = g_s2[tt];
    const float wa = g_wa[tt], wb = g_wb[tt];
    const float* p1 = (s1 >= 0) ? &g_sloth[((size_t)e1*SLOTS + s1)*DI] : (const float*)0;
    const float* p2 = (s2 >= 0) ? &g_sloth[((size_t)e2*SLOTS + s2)*DI] : (const float*)0;
    float vals[8];
    float sum = 0.f;
    #pragma unroll
    for (int i = 0; i < 8; i++) {
        int c = threadIdx.x + i*256;
        float hv = 0.f;
        if (p1) hv += wa * (p1[c] + b1[e1*DI + c]);
        if (p2) hv += wb * (p2[c] + b1[e2*DI + c]);
        vals[i] = hv; sum += hv;
    }
    float mean = blk_sum(sum, sb) / DI;
    float s2s = 0.f;
    #pragma unroll
    for (int i = 0; i < 8; i++) { float d = vals[i]-mean; s2s += d*d; }
    float var = blk_sum(s2s, sb) / DI;
    float r = rsqrtf(var + EPSV);
    #pragma unroll
    for (int i = 0; i < 8; i++) {
        int c = threadIdx.x + i*256;
        float v = fmaxf((vals[i]-mean)*r*lng[c] + lnb[c], 0.f);
        g_hpost[(size_t)tt*DI + c] = __float2half_rn(v);
    }
}

// ---------------- combine MoE2 + bias + residual + FINAL LN (fused) ----------------
__global__ void combine2_ln_kernel(const float* __restrict__ b2, float* __restrict__ out,
                                   const float* __restrict__ gg, const float* __restrict__ bb)
{
    __shared__ float sb[32];
    const int tt = blockIdx.x;
    const int grp = tt >> 11, ti = tt & 2047;
    const int e1 = g_e1[tt], e2 = g_e2[tt], s1 = g_s1[tt], s2 = g_s2[tt];
    const float wa = g_wa[tt], wb = g_wb[tt];
    const int row = ((ti >> 8) * SEQ) + grp*256 + (ti & 255);
    float vals[4];
    float sum = 0.f;
    #pragma unroll
    for (int i = 0; i < 4; i++) {
        int c = threadIdx.x + i*128;
        float y = 0.f;
        if (s1 >= 0) y += wa * (g_sloty[((size_t)e1*SLOTS + s1)*DM + c] + b2[e1*DM + c]);
        if (s2 >= 0) y += wb * (g_sloty[((size_t)e2*SLOTS + s2)*DM + c] + b2[e2*DM + c]);
        y += g_res[(size_t)row*DM + c];
        vals[i] = y; sum += y;
    }
    float mean = blk_sum(sum, sb) / DM;
    float s2s = 0.f;
    #pragma unroll
    for (int i = 0; i < 4; i++) { float d = vals[i]-mean; s2s += d*d; }
    float var = blk_sum(s2s, sb) / DM;
    float r = rsqrtf(var + EPSV);
    #pragma unroll
    for (int i = 0; i < 4; i++) {
        int c = threadIdx.x + i*128;
        out[(size_t)row*DM + c] = (vals[i]-mean)*r*gg[c] + bb[c];
    }
}

__global__ void set_lnp_kernel(const float* a0, const float* a1, const float* a2, const float* a3,
                               const float* a4, const float* a5, const float* a6, const float* a7)
{
    g_lnp[0]=a0; g_lnp[1]=a1; g_lnp[2]=a2; g_lnp[3]=a3;
    g_lnp[4]=a4; g_lnp[5]=a5; g_lnp[6]=a6; g_lnp[7]=a7;
}

// ---------------- launch ----------------
extern "C" void kernel_launch(void* const* d_in, const int* in_sizes, int n_in,
                              void* d_out, int out_size)
{
    const float *x=0,*wq=0,*wk=0,*wv=0,*wo=0,*ln_attn_g=0,*ln_attn_b=0,*wg1=0,*w1=0,*b1=0,
                *w2=0,*b2=0,*ln_out_g=0,*ln_out_b=0;
    const float* ln2048[8] = {0,0,0,0,0,0,0,0};
    int c262=0,c512=0,c12k=0,c25m=0,c49k=0,c2k=0;
    for (int i = 0; i < n_in; i++) {
        const float* p = (const float*)d_in[i];
        switch (in_sizes[i]) {
            case 4194304: x = p; break;
            case 262144:
                if (c262==0) wq=p; else if (c262==1) wk=p; else if (c262==2) wv=p; else wo=p;
                c262++; break;
            case 512:
                if (c512==0) ln_attn_g=p; else if (c512==1) ln_attn_b=p;
                else if (c512==2) ln_out_g=p; else ln_out_b=p;
                c512++; break;
            case 12288:
                if (c12k==0) wg1=p; else b2=p;
                c12k++; break;
            case 25165824:
                if (c25m==0) w1=p; else w2=p;
                c25m++; break;
            case 49152:
                if (c49k==0) b1=p;
                c49k++; break;
            case 2048:
                if (c2k < 8) ln2048[c2k] = p;
                c2k++; break;
            default: break;
        }
    }

    float *p_q,*p_k,*p_v,*p_ctx,*p_tmp,*p_res,*p_sloth,*p_sloty;
    __half *p_resh,*p_wh1,*p_wh2,*p_hpost;
    int *p_rowg,*p_rowl;
    cudaGetSymbolAddress((void**)&p_q,     g_q);
    cudaGetSymbolAddress((void**)&p_k,     g_k);
    cudaGetSymbolAddress((void**)&p_v,     g_v);
    cudaGetSymbolAddress((void**)&p_ctx,   g_ctx);
    cudaGetSymbolAddress((void**)&p_tmp,   g_tmp);
    cudaGetSymbolAddress((void**)&p_res,   g_res);
    cudaGetSymbolAddress((void**)&p_resh,  g_resh);
    cudaGetSymbolAddress((void**)&p_wh1,   g_wh1);
    cudaGetSymbolAddress((void**)&p_wh2,   g_wh2);
    cudaGetSymbolAddress((void**)&p_sloth, g_sloth);
    cudaGetSymbolAddress((void**)&p_sloty, g_sloty);
    cudaGetSymbolAddress((void**)&p_hpost, g_hpost);
    cudaGetSymbolAddress((void**)&p_rowg,  g_rowg);
    cudaGetSymbolAddress((void**)&p_rowl,  g_rowl);

    float* out = (float*)d_out;

    cudaFuncSetAttribute(moe_hmma<DM, DI>, cudaFuncAttributeMaxDynamicSharedMemorySize, MOE_SMEM_BYTES);
    cudaFuncSetAttribute(moe_hmma<DI, DM>, cudaFuncAttributeMaxDynamicSharedMemorySize, MOE_SMEM_BYTES);

    // 0) weight prep + LN param table
    transpose_half<<<dim3(DI/32, DM/32, NE), dim3(32,8)>>>(w1, p_wh1, DM, DI);
    transpose_half<<<dim3(DM/32, DI/32, NE), dim3(32,8)>>>(w2, p_wh2, DI, DM);
    set_lnp_kernel<<<1,1>>>(ln2048[0],ln2048[1],ln2048[2],ln2048[3],
                            ln2048[4],ln2048[5],ln2048[6],ln2048[7]);

    // 1) QKV projections (fp32, fused launch)
    sgemm_qkv<<<dim3(DM/128, NROWS/128, 3), 256>>>(x, wq, wk, wv, p_q, p_k, p_v);

    // 2) attention (fp32, pipelined)
    attn_kernel<<<dim3(SEQ/64, NB*NH), 64>>>(p_q, p_k, p_v, p_ctx);

    // 3) output projection + relu + residual, then LN (exact + fp16 copy)
    sgemm128<<<dim3(DM/128, NROWS/128), 256>>>(p_ctx, wo, p_tmp, DM, DM, x, 1);
    ln_kernel<<<NROWS, 256>>>(p_tmp, p_res, p_resh, ln_attn_g, ln_attn_b, DM);

    // 4) routing
    gate_kernel<<<NTOK, 128>>>(p_res, wg1);
    assign_kernel<<<NGRP, NE*32>>>();

    // 5) MoE GEMM1, combine+LN+relu, GEMM2, combine+residual+final LN (fused)
    moe_hmma<DM, DI><<<dim3(DI/256, SLOTS/128, NE), 256, MOE_SMEM_BYTES>>>(p_resh, p_rowg, p_wh1, p_sloth);
    combine1_kernel<<<NTOK, 256>>>(b1);
    moe_hmma<DI, DM><<<dim3(DM/256, SLOTS/128, NE), 256, MOE_SMEM_BYTES>>>(p_hpost, p_rowl, p_wh2, p_sloty);
    combine2_ln_kernel<<<NTOK, 128>>>(b2, out, ln_out_g, ln_out_b);

    (void)out_size;
}

// round 7
// speedup vs baseline: 2.6967x; 1.0134x over previous
#include <cuda_runtime.h>
#include <cuda_fp16.h>
#include <cstdint>
#include <cstddef>

// ---------------- problem constants ----------------
#define NB    8
#define SEQ   1024
#define DM    512
#define NH    8
#define DI    2048
#define NE    24
#define CAP   171
#define TG    2048
#define NGRP  4
#define NROWS (NB*SEQ)      // 8192
#define NTOK  (NGRP*TG)     // 8192
#define SLOTS 768
#define GOFF  192
#define EPSV  1e-6f

typedef unsigned long long u64;

// ---------------- device scratch ----------------
__device__ float  g_q[NROWS*DM];
__device__ float  g_k[NROWS*DM];
__device__ float  g_v[NROWS*DM];
__device__ float  g_ctx[NROWS*DM];
__device__ float  g_tmp[NROWS*DM];
__device__ float  g_res[NROWS*DM];
__device__ __half g_resh[NROWS*DM];
__device__ __half g_wh1[(size_t)NE*DI*DM];
__device__ __half g_wh2[(size_t)NE*DM*DI];
__device__ float  g_sloth[(size_t)NE*SLOTS*DI];
__device__ float  g_sloty[(size_t)NE*SLOTS*DM];
__device__ __half g_hpost[(size_t)NTOK*DI];
__device__ int    g_e1[NTOK], g_e2[NTOK], g_s1[NTOK], g_s2[NTOK];
__device__ float  g_wa[NTOK], g_wb[NTOK];
__device__ int    g_rowg[NE*SLOTS];
__device__ int    g_rowl[NE*SLOTS];
__device__ const float* g_lnp[8];

// ---------------- PTX helpers ----------------
__device__ __forceinline__ uint32_t smem_cast(const void* p) {
    uint32_t a;
    asm("{ .reg .u64 t; cvta.to.shared.u64 t, %1; cvt.u32.u64 %0, t; }" : "=r"(a) : "l"(p));
    return a;
}
#define CP_ASYNC16(dst, src) \
    asm volatile("cp.async.cg.shared.global [%0], [%1], 16;" :: "r"(dst), "l"(src) : "memory")
#define CP_COMMIT() asm volatile("cp.async.commit_group;" ::: "memory")
#define CP_WAIT(n)  asm volatile("cp.async.wait_group %0;" :: "n"(n) : "memory")

__device__ __forceinline__ void mma_f16(float* d, const uint32_t* a, const uint32_t* b) {
    asm volatile(
        "mma.sync.aligned.m16n8k16.row.col.f32.f16.f16.f32 "
        "{%0,%1,%2,%3}, {%4,%5,%6,%7}, {%8,%9}, {%0,%1,%2,%3};"
        : "+f"(d[0]), "+f"(d[1]), "+f"(d[2]), "+f"(d[3])
        : "r"(a[0]), "r"(a[1]), "r"(a[2]), "r"(a[3]), "r"(b[0]), "r"(b[1]));
}

// ---- packed fp32x2 (Blackwell paired FMA pipe) ----
__device__ __forceinline__ u64 pack2(float lo, float hi) {
    u64 r; asm("mov.b64 %0, {%1,%2};" : "=l"(r) : "f"(lo), "f"(hi)); return r;
}
__device__ __forceinline__ float2 unpack2(u64 v) {
    float2 f; asm("mov.b64 {%0,%1}, %2;" : "=f"(f.x), "=f"(f.y) : "l"(v)); return f;
}
__device__ __forceinline__ u64 fma2(u64 a, u64 b, u64 c) {
    u64 d; asm("fma.rn.f32x2 %0, %1, %2, %3;" : "=l"(d) : "l"(a), "l"(b), "l"(c)); return d;
}
__device__ __forceinline__ u64 mul2(u64 a, u64 b) {
    u64 d; asm("mul.rn.f32x2 %0, %1, %2;" : "=l"(d) : "l"(a), "l"(b)); return d;
}

// ---------------- block reduction ----------------
__device__ __forceinline__ float blk_sum(float v, float* sb) {
    int lane = threadIdx.x & 31, wid = threadIdx.x >> 5;
    #pragma unroll
    for (int o = 16; o; o >>= 1) v += __shfl_down_sync(0xffffffffu, v, o);
    if (lane == 0) sb[wid] = v;
    __syncthreads();
    int nw = (blockDim.x + 31) >> 5;
    if (wid == 0) {
        float r = (lane < nw) ? sb[lane] : 0.f;
        #pragma unroll
        for (int o = 16; o; o >>= 1) r += __shfl_down_sync(0xffffffffu, r, o);
        if (lane == 0) sb[0] = r;
    }
    __syncthreads();
    float r = sb[0];
    __syncthreads();
    return r;
}

// ---------------- weight prep: W[e][k][n] float -> Wh[e][n][k] half ----------------
__global__ void transpose_half(const float* __restrict__ W, __half* __restrict__ Wh,
                               int K, int N)
{
    __shared__ float t[32][33];
    const int e = blockIdx.z;
    const int n0 = blockIdx.x * 32, k0 = blockIdx.y * 32;
    const float* We = W + (size_t)e * K * N;
    __half* Whe = Wh + (size_t)e * K * N;
    const int tx = threadIdx.x, ty = threadIdx.y;
    #pragma unroll
    for (int i = 0; i < 32; i += 8)
        t[ty + i][tx] = We[(size_t)(k0 + ty + i) * N + n0 + tx];
    __syncthreads();
    #pragma unroll
    for (int i = 0; i < 32; i += 8)
        Whe[(size_t)(n0 + ty + i) * K + k0 + tx] = __float2half_rn(t[tx][ty + i]);
}

// ---------------- dense fp32 SGEMM body (128x128x16, f32x2 packed FMA) ----------------
__device__ __forceinline__ void sgemm_body(const float* __restrict__ A, const float* __restrict__ B,
                                           float* __restrict__ C, int N, int K,
                                           const float* __restrict__ R, int epi,
                                           int bx, int by)
{
    __shared__ float As[16][128];
    __shared__ float Bs[16][128];
    const int tid = threadIdx.x;
    const int trow = tid >> 4, tcol = tid & 15;

    u64 acc2[8][4];
    #pragma unroll
    for (int i = 0; i < 8; i++)
        #pragma unroll
        for (int j = 0; j < 4; j++) acc2[i][j] = 0ull;   // two packed +0.0f

    const int aRow = tid >> 1, aCol = (tid & 1) * 8;
    const int bRow = tid >> 5, bCol = (tid & 31) * 4;
    const float* Ap = A + (size_t)(by*128 + aRow)*K + aCol;
    const float* Bp = B + (size_t)bRow*N + bx*128 + bCol;

    float4 a0 = *(const float4*)(Ap);
    float4 a1 = *(const float4*)(Ap + 4);
    float4 b0 = *(const float4*)(Bp);
    float4 b1 = *(const float4*)(Bp + (size_t)8*N);

    for (int k0 = 0; k0 < K; k0 += 16) {
        As[aCol+0][aRow]=a0.x; As[aCol+1][aRow]=a0.y; As[aCol+2][aRow]=a0.z; As[aCol+3][aRow]=a0.w;
        As[aCol+4][aRow]=a1.x; As[aCol+5][aRow]=a1.y; As[aCol+6][aRow]=a1.z; As[aCol+7][aRow]=a1.w;
        *(float4*)&Bs[bRow  ][bCol] = b0;
        *(float4*)&Bs[bRow+8][bCol] = b1;
        __syncthreads();
        if (k0 + 16 < K) {
            a0 = *(const float4*)(Ap + k0 + 16);
            a1 = *(const float4*)(Ap + k0 + 20);
            b0 = *(const float4*)(Bp + (size_t)(k0+16)*N);
            b1 = *(const float4*)(Bp + (size_t)(k0+24)*N);
        }
        #pragma unroll
        for (int kk = 0; kk < 16; kk++) {
            float4 ar0 = *(const float4*)&As[kk][trow*8];
            float4 ar1 = *(const float4*)&As[kk][trow*8+4];
            const u64* bp0 = (const u64*)&Bs[kk][tcol*4];
            const u64* bp1 = (const u64*)&Bs[kk][tcol*4+64];
            u64 bpk[4] = {bp0[0], bp0[1], bp1[0], bp1[1]};
            u64 ad[8];
            ad[0]=pack2(ar0.x,ar0.x); ad[1]=pack2(ar0.y,ar0.y);
            ad[2]=pack2(ar0.z,ar0.z); ad[3]=pack2(ar0.w,ar0.w);
            ad[4]=pack2(ar1.x,ar1.x); ad[5]=pack2(ar1.y,ar1.y);
            ad[6]=pack2(ar1.z,ar1.z); ad[7]=pack2(ar1.w,ar1.w);
            #pragma unroll
            for (int i = 0; i < 8; i++)
                #pragma unroll
                for (int j = 0; j < 4; j++)
                    acc2[i][j] = fma2(ad[i], bpk[j], acc2[i][j]);
        }
        __syncthreads();
    }
    #pragma unroll
    for (int i = 0; i < 8; i++) {
        int row = by*128 + trow*8 + i;
        #pragma unroll
        for (int g = 0; g < 2; g++) {
            int col = bx*128 + tcol*4 + g*64;
            float2 p0 = unpack2(acc2[i][g*2]);
            float2 p1 = unpack2(acc2[i][g*2+1]);
            float4 v = make_float4(p0.x, p0.y, p1.x, p1.y);
            if (epi == 1) {
                const float4 r = *(const float4*)&R[(size_t)row*N + col];
                v.x = fmaxf(v.x, 0.f) + r.x;
                v.y = fmaxf(v.y, 0.f) + r.y;
                v.z = fmaxf(v.z, 0.f) + r.z;
                v.w = fmaxf(v.w, 0.f) + r.w;
            }
            *(float4*)&C[(size_t)row*N + col] = v;
        }
    }
}

__global__ __launch_bounds__(256)
void sgemm128(const float* __restrict__ A, const float* __restrict__ B,
              float* __restrict__ C, int N, int K,
              const float* __restrict__ R, int epi)
{
    sgemm_body(A, B, C, N, K, R, epi, blockIdx.x, blockIdx.y);
}

__global__ __launch_bounds__(256)
void sgemm_qkv(const float* __restrict__ A,
               const float* __restrict__ Bq, const float* __restrict__ Bk, const float* __restrict__ Bv,
               float* __restrict__ Cq, float* __restrict__ Ck, float* __restrict__ Cv)
{
    const float* B = (blockIdx.z == 0) ? Bq : (blockIdx.z == 1) ? Bk : Bv;
    float*       C = (blockIdx.z == 0) ? Cq : (blockIdx.z == 1) ? Ck : Cv;
    sgemm_body(A, B, C, DM, DM, (const float*)0, 0, blockIdx.x, blockIdx.y);
}

// ---------------- MoE grouped GEMM via mma.sync fp16 (f32 acc) ----------------
#define APH 40
#define BPH 40
#define ABUFH (128*APH)
#define BBUFH (256*BPH)
#define MOE_SMEM_BYTES ((2*ABUFH + 2*BBUFH) * 2)   // 61440

template<int KDIM, int NDIM>
__global__ __launch_bounds__(256)
void moe_hmma(const __half* __restrict__ X, const int* __restrict__ rowmap,
              const __half* __restrict__ W, float* __restrict__ C)
{
    constexpr int NC = KDIM / 32;
    extern __shared__ __half smh[];
    __half* Abuf = smh;
    __half* Bbuf = smh + 2*ABUFH;

    const int tid = threadIdx.x;
    const int wid = tid >> 5, lane = tid & 31;
    const int wm = wid & 1, wn = wid >> 1;
    const int m0w = wm*64, n0w = wn*64;
    const int r = lane >> 2, cq = lane & 3;

    const int e  = blockIdx.z;
    const int mt = blockIdx.y;
    const int n0 = blockIdx.x * 256;

    const int rowA = tid >> 1, segA = tid & 1;
    int token = rowmap[e*SLOTS + mt*128 + rowA];
    if (token < 0) token = 0;
    const __half* srcA = X + (size_t)token * KDIM + segA*16;
    const uint32_t smA = smem_cast(Abuf) + (uint32_t)(rowA*APH + segA*16)*2;

    const int rowB = tid;
    const __half* srcB = W + ((size_t)e*NDIM + n0 + rowB) * KDIM;
    const uint32_t smB = smem_cast(Bbuf) + (uint32_t)(rowB*BPH)*2;

    float acc[4][8][4];
    #pragma unroll
    for (int mi = 0; mi < 4; mi++)
        #pragma unroll
        for (int ni = 0; ni < 8; ni++)
            #pragma unroll
            for (int q = 0; q < 4; q++) acc[mi][ni][q] = 0.f;

    auto load_chunk = [&](int c) {
        uint32_t da = smA + (uint32_t)(c & 1)*(ABUFH*2);
        const __half* sa = srcA + c*32;
        CP_ASYNC16(da,      sa);
        CP_ASYNC16(da + 16, sa + 8);
        uint32_t db = smB + (uint32_t)(c & 1)*(BBUFH*2);
        const __half* sb2 = srcB + c*32;
        #pragma unroll
        for (int i = 0; i < 4; i++) CP_ASYNC16(db + i*16, sb2 + i*8);
        CP_COMMIT();
    };

    load_chunk(0);
    for (int c = 0; c < NC; c++) {
        if (c + 1 < NC) { load_chunk(c + 1); CP_WAIT(1); }
        else           { CP_WAIT(0); }
        __syncthreads();

        const __half* As_ = Abuf + (c & 1)*ABUFH;
        const __half* Bs_ = Bbuf + (c & 1)*BBUFH;
        #pragma unroll
        for (int ks = 0; ks < 2; ks++) {
            const int k0 = ks*16 + cq*2;
            uint32_t a[4][4];
            #pragma unroll
            for (int mi = 0; mi < 4; mi++) {
                int m = m0w + mi*16 + r;
                a[mi][0] = *(const uint32_t*)&As_[m*APH + k0];
                a[mi][1] = *(const uint32_t*)&As_[(m+8)*APH + k0];
                a[mi][2] = *(const uint32_t*)&As_[m*APH + k0 + 8];
                a[mi][3] = *(const uint32_t*)&As_[(m+8)*APH + k0 + 8];
            }
            uint32_t b[8][2];
            #pragma unroll
            for (int ni = 0; ni < 8; ni++) {
                int n = n0w + ni*8 + r;
                b[ni][0] = *(const uint32_t*)&Bs_[n*BPH + k0];
                b[ni][1] = *(const uint32_t*)&Bs_[n*BPH + k0 + 8];
            }
            #pragma unroll
            for (int mi = 0; mi < 4; mi++)
                #pragma unroll
                for (int ni = 0; ni < 8; ni++)
                    mma_f16(acc[mi][ni], a[mi], b[ni]);
        }
        __syncthreads();
    }

    #pragma unroll
    for (int mi = 0; mi < 4; mi++) {
        int mrow = mt*128 + m0w + mi*16 + r;
        float* C0 = C + ((size_t)e*SLOTS + mrow    )*NDIM + n0 + n0w;
        float* C1 = C + ((size_t)e*SLOTS + mrow + 8)*NDIM + n0 + n0w;
        #pragma unroll
        for (int ni = 0; ni < 8; ni++) {
            int col = ni*8 + 2*cq;
            *(float2*)(C0 + col) = make_float2(acc[mi][ni][0], acc[mi][ni][1]);
            *(float2*)(C1 + col) = make_float2(acc[mi][ni][2], acc[mi][ni][3]);
        }
    }
}

// ---------------- attention (fp32, f32x2 packed FMA, cp.async pipelined) ----------------
__global__ __launch_bounds__(64)
void attn_kernel(const float* __restrict__ Q, const float* __restrict__ K,
                 const float* __restrict__ V, float* __restrict__ O)
{
    __shared__ float Ks[2][32][64];
    __shared__ float Vs[2][32][64];
    const int bh = blockIdx.y;
    const int b = bh / NH, h = bh % NH;
    const int qi = blockIdx.x*64 + threadIdx.x;
    const size_t qoff = ((size_t)(b*SEQ + qi))*DM + h*64;
    const size_t kbase = ((size_t)b*SEQ)*DM + h*64;

    const uint32_t sK = smem_cast(Ks);
    const uint32_t sV = smem_cast(Vs);

    u64 q2[32];
    #pragma unroll
    for (int d = 0; d < 64; d += 4) {
        float4 t = *(const float4*)&Q[qoff + d];
        q2[d/2]   = pack2(t.x*0.125f, t.y*0.125f);
        q2[d/2+1] = pack2(t.z*0.125f, t.w*0.125f);
    }
    float m = -1e30f, l = 0.f;
    u64 o2[32];
    #pragma unroll
    for (int d2 = 0; d2 < 32; d2++) o2[d2] = 0ull;

    auto load_tile = [&](int kt, int buf) {
        #pragma unroll
        for (int it = 0; it < 8; it++) {
            int f = threadIdx.x + it*64;
            int j = f >> 4; int d4 = (f & 15)*4;
            uint32_t off = (uint32_t)(buf*8192 + (j*64 + d4)*4);
            size_t src = kbase + (size_t)(kt + j)*DM + d4;
            CP_ASYNC16(sK + off, &K[src]);
            CP_ASYNC16(sV + off, &V[src]);
        }
        CP_COMMIT();
    };

    load_tile(0, 0);
    for (int t = 0; t < SEQ/32; t++) {
        const int buf = t & 1;
        if (t + 1 < SEQ/32) { load_tile((t+1)*32, (t+1) & 1); CP_WAIT(1); }
        else                { CP_WAIT(0); }
        __syncthreads();

        float s[32];
        #pragma unroll
        for (int j = 0; j < 32; j++) {
            const u64* kp = (const u64*)&Ks[buf][j][0];
            u64 accA = 0ull, accB = 0ull;          // accA: d%4 in {0,1}; accB: {2,3}
            #pragma unroll
            for (int d2 = 0; d2 < 32; d2 += 2) {
                accA = fma2(q2[d2],   kp[d2],   accA);
                accB = fma2(q2[d2+1], kp[d2+1], accB);
            }
            float2 fa = unpack2(accA), fb = unpack2(accB);
            s[j] = (fa.x + fa.y) + (fb.x + fb.y);  // same grouping as (a0+a1)+(a2+a3)
        }
        float tmax = m;
        #pragma unroll
        for (int j = 0; j < 32; j++) tmax = fmaxf(tmax, s[j]);
        float f = __expf(m - tmax);
        l *= f;
        u64 f2 = pack2(f, f);
        #pragma unroll
        for (int d2 = 0; d2 < 32; d2++) o2[d2] = mul2(o2[d2], f2);
        #pragma unroll
        for (int j = 0; j < 32; j++) {
            float p = __expf(s[j] - tmax);
            l += p;
            u64 p2v = pack2(p, p);
            const u64* vp = (const u64*)&Vs[buf][j][0];
            #pragma unroll
            for (int d2 = 0; d2 < 32; d2++) o2[d2] = fma2(p2v, vp[d2], o2[d2]);
        }
        m = tmax;
        __syncthreads();
    }
    float inv = 1.f / l;
    #pragma unroll
    for (int d2 = 0; d2 < 32; d2 += 2) {
        float2 pa = unpack2(o2[d2]), pb = unpack2(o2[d2+1]);
        *(float4*)&O[qoff + d2*2] = make_float4(pa.x*inv, pa.y*inv, pb.x*inv, pb.y*inv);
    }
}

// ---------------- layernorm (optional fp16 second output) ----------------
__global__ void ln_kernel(const float* __restrict__ X, float* __restrict__ Y,
                          __half* __restrict__ Yh,
                          const float* __restrict__ gg, const float* __restrict__ bb, int len)
{
    __shared__ float sb[32];
    const int row = blockIdx.x;
    const float* xr = X + (size_t)row*len;
    float sum = 0.f;
    for (int c = threadIdx.x; c < len; c += blockDim.x) sum += xr[c];
    float mean = blk_sum(sum, sb) / len;
    float s2 = 0.f;
    for (int c = threadIdx.x; c < len; c += blockDim.x) { float d = xr[c]-mean; s2 += d*d; }
    float var = blk_sum(s2, sb) / len;
    float r = rsqrtf(var + EPSV);
    for (int c = threadIdx.x; c < len; c += blockDim.x) {
        float v = (xr[c]-mean)*r*gg[c] + bb[c];
        Y[(size_t)row*len + c] = v;
        if (Yh) Yh[(size_t)row*len + c] = __float2half_rn(v);
    }
}

// ---------------- gating (fp32 exact — unchanged) ----------------
__global__ void gate_kernel(const float* __restrict__ Xres, const float* __restrict__ wg)
{
    __shared__ float xr[DM];
    __shared__ float lg[NE];
    const int tt = blockIdx.x;
    const int grp = tt >> 11, ti = tt & 2047;
    const int row = ((ti >> 8) * SEQ) + grp*256 + (ti & 255);
    for (int c = threadIdx.x; c < DM; c += blockDim.x) xr[c] = Xres[(size_t)row*DM + c];
    __syncthreads();
    if (threadIdx.x < NE) {
        float acc = 0.f;
        #pragma unroll 8
        for (int d = 0; d < DM; d++) acc = fmaf(xr[d], wg[d*NE + threadIdx.x], acc);
        lg[threadIdx.x] = acc;
    }
    __syncthreads();
    if (threadIdx.x == 0) {
        int i1 = 0; float v1 = lg[0];
        for (int e2 = 1; e2 < NE; e2++) if (lg[e2] > v1) { v1 = lg[e2]; i1 = e2; }
        int i2 = -1; float v2 = -1e30f;
        for (int e2 = 0; e2 < NE; e2++) if (e2 != i1 && lg[e2] > v2) { v2 = lg[e2]; i2 = e2; }
        float r2 = expf(v2 - v1);
        float inv = 1.f / (1.f + r2);
        g_e1[tt] = i1; g_e2[tt] = i2;
        g_wa[tt] = inv; g_wb[tt] = r2 * inv;
    }
}

// ---------------- GShard slot assignment ----------------
__global__ void assign_kernel()
{
    __shared__ int scnt[NE];
    const int grp = blockIdx.x;
    const int tid = threadIdx.x, lane = tid & 31, e = tid >> 5;
    for (int i = tid; i < NE*GOFF; i += blockDim.x) {
        int ee = i / GOFF, s = i % GOFF;
        g_rowg[ee*SLOTS + grp*GOFF + s] = -1;
        g_rowl[ee*SLOTS + grp*GOFF + s] = -1;
    }
    __syncthreads();
    int cnt = 0;
    for (int base = 0; base < TG; base += 32) {
        int ti = base + lane;
        int tt = grp*TG + ti;
        bool mm = (g_e1[tt] == e);
        unsigned bal = __ballot_sync(0xffffffffu, mm);
        if (mm) {
            int loc = cnt + __popc(bal & ((1u << lane) - 1u));
            if (loc < CAP) {
                int srow = grp*GOFF + loc;
                g_s1[tt] = srow;
                int row = ((ti >> 8) * SEQ) + grp*256 + (ti & 255);
                g_rowg[e*SLOTS + srow] = row;
                g_rowl[e*SLOTS + srow] = tt;
            } else g_s1[tt] = -1;
        }
        cnt += __popc(bal);
    }
    if (lane == 0) scnt[e] = cnt;
    __syncthreads();
    cnt = scnt[e];
    for (int base = 0; base < TG; base += 32) {
        int ti = base + lane;
        int tt = grp*TG + ti;
        bool mm = (g_e2[tt] == e);
        unsigned bal = __ballot_sync(0xffffffffu, mm);
        if (mm) {
            int loc = cnt + __popc(bal & ((1u << lane) - 1u));
            if (loc < CAP) {
                int srow = grp*GOFF + loc;
                g_s2[tt] = srow;
                int row = ((ti >> 8) * SEQ) + grp*256 + (ti & 255);
                g_rowg[e*SLOTS + srow] = row;
                g_rowl[e*SLOTS + srow] = tt;
            } else g_s2[tt] = -1;
        }
        cnt += __popc(bal);
    }
}

// ---------------- combine MoE1 + bias + LN + relu -> fp16 ----------------
__global__ void combine1_kernel(const float* __restrict__ b1)
{
    __shared__ float sb[32];
    const int tt = blockIdx.x;
    const int grp = tt >> 11;
    const float* lng = g_lnp[2*grp];
    const float* lnb = g_lnp[2*grp+1];
    const int e1 = g_e1[tt], e2 = g_e2[tt], s1 = g_s1[tt], s2 = g_s2[tt];
    const float wa = g_wa[tt], wb = g_wb[tt];
    const float* p1 = (s1 >= 0) ? &g_sloth[((size_t)e1*SLOTS + s1)*DI] : (const float*)0;
    const float* p2 = (s2 >= 0) ? &g_sloth[((size_t)e2*SLOTS + s2)*DI] : (const float*)0;
    float vals[8];
    float sum = 0.f;
    #pragma unroll
    for (int i = 0; i < 8; i++) {
        int c = threadIdx.x + i*256;
        float hv = 0.f;
        if (p1) hv += wa * (p1[c] + b1[e1*DI + c]);
        if (p2) hv += wb * (p2[c] + b1[e2*DI + c]);
        vals[i] = hv; sum += hv;
    }
    float mean = blk_sum(sum, sb) / DI;
    float s2s = 0.f;
    #pragma unroll
    for (int i = 0; i < 8; i++) { float d = vals[i]-mean; s2s += d*d; }
    float var = blk_sum(s2s, sb) / DI;
    float r = rsqrtf(var + EPSV);
    #pragma unroll
    for (int i = 0; i < 8; i++) {
        int c = threadIdx.x + i*256;
        float v = fmaxf((vals[i]-mean)*r*lng[c] + lnb[c], 0.f);
        g_hpost[(size_t)tt*DI + c] = __float2half_rn(v);
    }
}

// ---------------- combine MoE2 + bias + residual + FINAL LN (fused) ----------------
__global__ void combine2_ln_kernel(const float* __restrict__ b2, float* __restrict__ out,
                                   const float* __restrict__ gg, const float* __restrict__ bb)
{
    __shared__ float sb[32];
    const int tt = blockIdx.x;
    const int grp = tt >> 11, ti = tt & 2047;
    const int e1 = g_e1[tt], e2 = g_e2[tt], s1 = g_s1[tt], s2 = g_s2[tt];
    const float wa = g_wa[tt], wb = g_wb[tt];
    const int row = ((ti >> 8) * SEQ) + grp*256 + (ti & 255);
    float vals[4];
    float sum = 0.f;
    #pragma unroll
    for (int i = 0; i < 4; i++) {
        int c = threadIdx.x + i*128;
        float y = 0.f;
        if (s1 >= 0) y += wa * (g_sloty[((size_t)e1*SLOTS + s1)*DM + c] + b2[e1*DM + c]);
        if (s2 >= 0) y += wb * (g_sloty[((size_t)e2*SLOTS + s2)*DM + c] + b2[e2*DM + c]);
        y += g_res[(size_t)row*DM + c];
        vals[i] = y; sum += y;
    }
    float mean = blk_sum(sum, sb) / DM;
    float s2s = 0.f;
    #pragma unroll
    for (int i = 0; i < 4; i++) { float d = vals[i]-mean; s2s += d*d; }
    float var = blk_sum(s2s, sb) / DM;
    float r = rsqrtf(var + EPSV);
    #pragma unroll
    for (int i = 0; i < 4; i++) {
        int c = threadIdx.x + i*128;
        out[(size_t)row*DM + c] = (vals[i]-mean)*r*gg[c] + bb[c];
    }
}

__global__ void set_lnp_kernel(const float* a0, const float* a1, const float* a2, const float* a3,
                               const float* a4, const float* a5, const float* a6, const float* a7)
{
    g_lnp[0]=a0; g_lnp[1]=a1; g_lnp[2]=a2; g_lnp[3]=a3;
    g_lnp[4]=a4; g_lnp[5]=a5; g_lnp[6]=a6; g_lnp[7]=a7;
}

// ---------------- launch ----------------
extern "C" void kernel_launch(void* const* d_in, const int* in_sizes, int n_in,
                              void* d_out, int out_size)
{
    const float *x=0,*wq=0,*wk=0,*wv=0,*wo=0,*ln_attn_g=0,*ln_attn_b=0,*wg1=0,*w1=0,*b1=0,
                *w2=0,*b2=0,*ln_out_g=0,*ln_out_b=0;
    const float* ln2048[8] = {0,0,0,0,0,0,0,0};
    int c262=0,c512=0,c12k=0,c25m=0,c49k=0,c2k=0;
    for (int i = 0; i < n_in; i++) {
        const float* p = (const float*)d_in[i];
        switch (in_sizes[i]) {
            case 4194304: x = p; break;
            case 262144:
                if (c262==0) wq=p; else if (c262==1) wk=p; else if (c262==2) wv=p; else wo=p;
                c262++; break;
            case 512:
                if (c512==0) ln_attn_g=p; else if (c512==1) ln_attn_b=p;
                else if (c512==2) ln_out_g=p; else ln_out_b=p;
                c512++; break;
            case 12288:
                if (c12k==0) wg1=p; else b2=p;
                c12k++; break;
            case 25165824:
                if (c25m==0) w1=p; else w2=p;
                c25m++; break;
            case 49152:
                if (c49k==0) b1=p;
                c49k++; break;
            case 2048:
                if (c2k < 8) ln2048[c2k] = p;
                c2k++; break;
            default: break;
        }
    }

    float *p_q,*p_k,*p_v,*p_ctx,*p_tmp,*p_res,*p_sloth,*p_sloty;
    __half *p_resh,*p_wh1,*p_wh2,*p_hpost;
    int *p_rowg,*p_rowl;
    cudaGetSymbolAddress((void**)&p_q,     g_q);
    cudaGetSymbolAddress((void**)&p_k,     g_k);
    cudaGetSymbolAddress((void**)&p_v,     g_v);
    cudaGetSymbolAddress((void**)&p_ctx,   g_ctx);
    cudaGetSymbolAddress((void**)&p_tmp,   g_tmp);
    cudaGetSymbolAddress((void**)&p_res,   g_res);
    cudaGetSymbolAddress((void**)&p_resh,  g_resh);
    cudaGetSymbolAddress((void**)&p_wh1,   g_wh1);
    cudaGetSymbolAddress((void**)&p_wh2,   g_wh2);
    cudaGetSymbolAddress((void**)&p_sloth, g_sloth);
    cudaGetSymbolAddress((void**)&p_sloty, g_sloty);
    cudaGetSymbolAddress((void**)&p_hpost, g_hpost);
    cudaGetSymbolAddress((void**)&p_rowg,  g_rowg);
    cudaGetSymbolAddress((void**)&p_rowl,  g_rowl);

    float* out = (float*)d_out;

    cudaFuncSetAttribute(moe_hmma<DM, DI>, cudaFuncAttributeMaxDynamicSharedMemorySize, MOE_SMEM_BYTES);
    cudaFuncSetAttribute(moe_hmma<DI, DM>, cudaFuncAttributeMaxDynamicSharedMemorySize, MOE_SMEM_BYTES);

    // 0) weight prep + LN param table
    transpose_half<<<dim3(DI/32, DM/32, NE), dim3(32,8)>>>(w1, p_wh1, DM, DI);
    transpose_half<<<dim3(DM/32, DI/32, NE), dim3(32,8)>>>(w2, p_wh2, DI, DM);
    set_lnp_kernel<<<1,1>>>(ln2048[0],ln2048[1],ln2048[2],ln2048[3],
                            ln2048[4],ln2048[5],ln2048[6],ln2048[7]);

    // 1) QKV projections (fp32 f32x2, fused launch)
    sgemm_qkv<<<dim3(DM/128, NROWS/128, 3), 256>>>(x, wq, wk, wv, p_q, p_k, p_v);

    // 2) attention (fp32 f32x2, pipelined)
    attn_kernel<<<dim3(SEQ/64, NB*NH), 64>>>(p_q, p_k, p_v, p_ctx);

    // 3) output projection + relu + residual, then LN (exact + fp16 copy)
    sgemm128<<<dim3(DM/128, NROWS/128), 256>>>(p_ctx, wo, p_tmp, DM, DM, x, 1);
    ln_kernel<<<NROWS, 256>>>(p_tmp, p_res, p_resh, ln_attn_g, ln_attn_b, DM);

    // 4) routing
    gate_kernel<<<NTOK, 128>>>(p_res, wg1);
    assign_kernel<<<NGRP, NE*32>>>();

    // 5) MoE GEMM1, combine+LN+relu, GEMM2, combine+residual+final LN (fused)
    moe_hmma<DM, DI><<<dim3(DI/256, SLOTS/128, NE), 256, MOE_SMEM_BYTES>>>(p_resh, p_rowg, p_wh1, p_sloth);
    combine1_kernel<<<NTOK, 256>>>(b1);
    moe_hmma<DI, DM><<<dim3(DM/256, SLOTS/128, NE), 256, MOE_SMEM_BYTES>>>(p_hpost, p_rowl, p_wh2, p_sloty);
    combine2_ln_kernel<<<NTOK, 128>>>(b2, out, ln_out_g, ln_out_b);

    (void)out_size;
}